// round 2
// baseline (speedup 1.0000x reference)
#include <cuda_runtime.h>

// Problem constants
#define BB 8
#define LL 1024
#define DD 1024
#define HH 4
#define DH 256          // head dim = DD/HH
#define GW 2047         // generator width = 2*MAX_LEN-1 (L == MAX_LEN -> full window)
#define TK 16

// Scratch (device globals; no allocation allowed)
__device__ float g_q[BB * LL * DD];            // 33.5 MB
__device__ float g_v[BB * LL * DD];            // 33.5 MB
__device__ float g_w[BB * HH * LL * LL];       // 134 MB
__device__ float g_attn[BB * LL * DD];         // 33.5 MB
__device__ float g_rs[BB * HH * LL];

// ---------------------------------------------------------------------------
// C[M,N] = A[M,K] @ B[N,K]^T   (row-major, all dims multiples of 64/16)
// 64x64 tile, 16x16 threads, 4x4 micro-tile, TK=16
// ---------------------------------------------------------------------------
__global__ __launch_bounds__(256) void gemm_nt(
    const float* __restrict__ A, const float* __restrict__ Bm,
    float* __restrict__ C, int M, int N, int K) {
    __shared__ float As[TK][68];
    __shared__ float Bs[TK][68];
    const int tx = threadIdx.x, ty = threadIdx.y;
    const int tid = ty * 16 + tx;
    const int m0 = blockIdx.y * 64, n0 = blockIdx.x * 64;
    const int r = tid >> 2, qd = (tid & 3) * 4;
    float acc[4][4] = {};
    for (int k0 = 0; k0 < K; k0 += TK) {
        float4 a = *(const float4*)(A + (size_t)(m0 + r) * K + k0 + qd);
        float4 b = *(const float4*)(Bm + (size_t)(n0 + r) * K + k0 + qd);
        __syncthreads();
        As[qd + 0][r] = a.x; As[qd + 1][r] = a.y; As[qd + 2][r] = a.z; As[qd + 3][r] = a.w;
        Bs[qd + 0][r] = b.x; Bs[qd + 1][r] = b.y; Bs[qd + 2][r] = b.z; Bs[qd + 3][r] = b.w;
        __syncthreads();
#pragma unroll
        for (int kk = 0; kk < TK; kk++) {
            float4 av = *(const float4*)&As[kk][ty * 4];
            float4 bv = *(const float4*)&Bs[kk][tx * 4];
            acc[0][0] += av.x * bv.x; acc[0][1] += av.x * bv.y; acc[0][2] += av.x * bv.z; acc[0][3] += av.x * bv.w;
            acc[1][0] += av.y * bv.x; acc[1][1] += av.y * bv.y; acc[1][2] += av.y * bv.z; acc[1][3] += av.y * bv.w;
            acc[2][0] += av.z * bv.x; acc[2][1] += av.z * bv.y; acc[2][2] += av.z * bv.z; acc[2][3] += av.z * bv.w;
            acc[3][0] += av.w * bv.x; acc[3][1] += av.w * bv.y; acc[3][2] += av.w * bv.z; acc[3][3] += av.w * bv.w;
        }
    }
#pragma unroll
    for (int a = 0; a < 4; a++) {
        float4 o = make_float4(acc[a][0], acc[a][1], acc[a][2], acc[a][3]);
        *(float4*)(C + (size_t)(m0 + ty * 4 + a) * N + n0 + tx * 4) = o;
    }
}

// ---------------------------------------------------------------------------
// Toeplitz score GEMM (gather fused):
//   g_w[bh, l, i] = sum_k q[b, l, h*DH+k] * gen[h, k, (L-1) - l + i]
// Tile: 64(l) x 64(i), K-chunk 16. Gen tile needs 127 contiguous cols.
// ---------------------------------------------------------------------------
__global__ __launch_bounds__(256) void toeplitz_w(
    const float* __restrict__ q, const float* __restrict__ gen) {
    const int bh = blockIdx.z;
    const int b = bh >> 2, h = bh & 3;
    const int l0 = blockIdx.y * 64, i0 = blockIdx.x * 64;
    const int tx = threadIdx.x, ty = threadIdx.y;
    const int tid = ty * 16 + tx;
    __shared__ float qs[TK][68];
    __shared__ float gs[TK][128];
    const int cbase = (LL - 1) - l0 - 63 + i0;   // gen col of local index 0
    const int r = tid >> 2, qd = (tid & 3) * 4;
    const float* __restrict__ genh = gen + (size_t)h * DH * GW;
    float acc[4][4] = {};
    for (int k0 = 0; k0 < DH; k0 += TK) {
        float4 a = *(const float4*)(q + (size_t)(b * LL + l0 + r) * DD + h * DH + k0 + qd);
        __syncthreads();
        qs[qd + 0][r] = a.x; qs[qd + 1][r] = a.y; qs[qd + 2][r] = a.z; qs[qd + 3][r] = a.w;
#pragma unroll
        for (int t = tid; t < TK * 128; t += 256) {
            int kk = t >> 7, cc = t & 127;
            int gc = cbase + cc;
            gs[kk][cc] = (gc < GW) ? genh[(size_t)(k0 + kk) * GW + gc] : 0.f;
        }
        __syncthreads();
#pragma unroll
        for (int kk = 0; kk < TK; kk++) {
            float q0 = qs[kk][ty * 4 + 0];
            float q1 = qs[kk][ty * 4 + 1];
            float q2 = qs[kk][ty * 4 + 2];
            float q3 = qs[kk][ty * 4 + 3];
            const int gb = 60 - ty * 4 + tx * 4;
            float gv[7];
#pragma unroll
            for (int j = 0; j < 7; j++) gv[j] = gs[kk][gb + j];
            // acc[a][b] += q_a * gv[3 - a + b]
            acc[0][0] += q0 * gv[3]; acc[0][1] += q0 * gv[4]; acc[0][2] += q0 * gv[5]; acc[0][3] += q0 * gv[6];
            acc[1][0] += q1 * gv[2]; acc[1][1] += q1 * gv[3]; acc[1][2] += q1 * gv[4]; acc[1][3] += q1 * gv[5];
            acc[2][0] += q2 * gv[1]; acc[2][1] += q2 * gv[2]; acc[2][2] += q2 * gv[3]; acc[2][3] += q2 * gv[4];
            acc[3][0] += q3 * gv[0]; acc[3][1] += q3 * gv[1]; acc[3][2] += q3 * gv[2]; acc[3][3] += q3 * gv[3];
        }
    }
#pragma unroll
    for (int a = 0; a < 4; a++) {
        float4 o = make_float4(acc[a][0], acc[a][1], acc[a][2], acc[a][3]);
        *(float4*)(g_w + (size_t)(bh * LL + l0 + ty * 4 + a) * LL + i0 + tx * 4) = o;
    }
}

// ---------------------------------------------------------------------------
// cumsum over l (axis=2), then relu, then causal mask (i<=l). In place.
// One thread per (bh, i); unroll-8 for memory-level parallelism.
// ---------------------------------------------------------------------------
__global__ __launch_bounds__(256) void cumsum_relu_mask() {
    const int bh = blockIdx.y;
    const int i = blockIdx.x * 256 + threadIdx.x;
    float* __restrict__ W = g_w + (size_t)bh * (LL * LL) + i;
    float acc = 0.f;
    for (int l = 0; l < LL; l += 8) {
        float vb[8];
#pragma unroll
        for (int u = 0; u < 8; u++) vb[u] = W[(size_t)(l + u) * LL];
#pragma unroll
        for (int u = 0; u < 8; u++) {
            acc += vb[u];
            W[(size_t)(l + u) * LL] = (i <= l + u) ? fmaxf(acc, 0.f) : 0.f;
        }
    }
}

// ---------------------------------------------------------------------------
// Row sums of the masked/relu'd W (only i <= l are nonzero).
// ---------------------------------------------------------------------------
__global__ __launch_bounds__(256) void rowsum_k() {
    const int bh = blockIdx.y, l = blockIdx.x;
    const float* __restrict__ W = g_w + (size_t)(bh * LL + l) * LL;
    float s = 0.f;
    for (int i = threadIdx.x; i <= l; i += 256) s += W[i];
#pragma unroll
    for (int o = 16; o > 0; o >>= 1) s += __shfl_xor_sync(0xffffffffu, s, o);
    __shared__ float red[8];
    if ((threadIdx.x & 31) == 0) red[threadIdx.x >> 5] = s;
    __syncthreads();
    if (threadIdx.x < 8) {
        s = red[threadIdx.x];
#pragma unroll
        for (int o = 4; o > 0; o >>= 1) s += __shfl_xor_sync(0xffu, s, o);
        if (threadIdx.x == 0) g_rs[bh * LL + l] = s;
    }
}

// ---------------------------------------------------------------------------
// attn[b,l,h,:] = (1/(rowsum+1e-8)) * sum_i W[bh,l,i] * v[b,i,h,:]
// Causal: only i < l0+64 tiles contribute (upper part stored as zeros).
// ---------------------------------------------------------------------------
__global__ __launch_bounds__(256) void av_gemm() {
    const int bh = blockIdx.z, b = bh >> 2, h = bh & 3;
    const int l0 = blockIdx.y * 64, n0 = blockIdx.x * 64;   // n over DH
    const int tx = threadIdx.x, ty = threadIdx.y;
    const int tid = ty * 16 + tx;
    __shared__ float As[TK][68];
    __shared__ float Bs[TK][68];
    const int r = tid >> 2, qd = (tid & 3) * 4;
    const int kk2 = tid >> 4, nc = (tid & 15) * 4;
    float acc[4][4] = {};
    const int kend = l0 + 64;
    for (int i0 = 0; i0 < kend; i0 += TK) {
        float4 a = *(const float4*)(g_w + (size_t)(bh * LL + l0 + r) * LL + i0 + qd);
        float4 bv = *(const float4*)(g_v + (size_t)(b * LL + i0 + kk2) * DD + h * DH + n0 + nc);
        __syncthreads();
        As[qd + 0][r] = a.x; As[qd + 1][r] = a.y; As[qd + 2][r] = a.z; As[qd + 3][r] = a.w;
        *(float4*)&Bs[kk2][nc] = bv;
        __syncthreads();
#pragma unroll
        for (int kk = 0; kk < TK; kk++) {
            float4 av = *(const float4*)&As[kk][ty * 4];
            float4 bw = *(const float4*)&Bs[kk][tx * 4];
            acc[0][0] += av.x * bw.x; acc[0][1] += av.x * bw.y; acc[0][2] += av.x * bw.z; acc[0][3] += av.x * bw.w;
            acc[1][0] += av.y * bw.x; acc[1][1] += av.y * bw.y; acc[1][2] += av.y * bw.z; acc[1][3] += av.y * bw.w;
            acc[2][0] += av.z * bw.x; acc[2][1] += av.z * bw.y; acc[2][2] += av.z * bw.z; acc[2][3] += av.z * bw.w;
            acc[3][0] += av.w * bw.x; acc[3][1] += av.w * bw.y; acc[3][2] += av.w * bw.z; acc[3][3] += av.w * bw.w;
        }
    }
#pragma unroll
    for (int a = 0; a < 4; a++) {
        const int row = l0 + ty * 4 + a;
        const float s = 1.f / (g_rs[bh * LL + row] + 1e-8f);
        float4 o = make_float4(acc[a][0] * s, acc[a][1] * s, acc[a][2] * s, acc[a][3] * s);
        *(float4*)(g_attn + (size_t)(b * LL + row) * DD + h * DH + n0 + tx * 4) = o;
    }
}

// ---------------------------------------------------------------------------
extern "C" void kernel_launch(void* const* d_in, const int* in_sizes, int n_in,
                              void* d_out, int out_size) {
    const float* x   = (const float*)d_in[0];   // (B, L, D)
    const float* gen = (const float*)d_in[1];   // (H, DH, 2047)
    const float* Wq  = (const float*)d_in[2];   // (D, D)
    const float* Wv  = (const float*)d_in[3];   // (D, D)
    const float* Wp  = (const float*)d_in[4];   // (D, D)
    float* out = (float*)d_out;                 // (B, L, D)

    float *qp, *vp, *ap;
    cudaGetSymbolAddress((void**)&qp, g_q);
    cudaGetSymbolAddress((void**)&vp, g_v);
    cudaGetSymbolAddress((void**)&ap, g_attn);

    const int M = BB * LL;          // 8192
    dim3 blk(16, 16);
    dim3 grid_proj(DD / 64, M / 64);    // (16, 128)

    // 1-2) q = x @ Wq^T ; v = x @ Wv^T
    gemm_nt<<<grid_proj, blk>>>(x, Wq, qp, M, DD, DD);
    gemm_nt<<<grid_proj, blk>>>(x, Wv, vp, M, DD, DD);

    // 3) Toeplitz-gathered scores W[bh,l,i]
    toeplitz_w<<<dim3(LL / 64, LL / 64, BB * HH), blk>>>(qp, gen);

    // 4) cumsum over l + relu + causal mask (in place)
    cumsum_relu_mask<<<dim3(LL / 256, BB * HH), 256>>>();

    // 5) row sums for normalization
    rowsum_k<<<dim3(LL, BB * HH), 256>>>();

    // 6) attn = normalize(W) @ v   (causal, fused 1/rowsum epilogue)
    av_gemm<<<dim3(DH / 64, LL / 64, BB * HH), blk>>>();

    // 7) out = attn @ Wproj^T
    gemm_nt<<<grid_proj, blk>>>(ap, Wp, out, M, DD, DD);
}

// round 3
// speedup vs baseline: 1.0717x; 1.0717x over previous
#include <cuda_runtime.h>

// Problem constants
#define BB 8
#define LL 1024
#define DD 1024
#define HH 4
#define DH 256          // head dim
#define GW 2047         // generator width (full window since L == MAX_LEN)

// Scratch (device globals; no allocation allowed)
__device__ float g_q[BB * LL * DD];
__device__ float g_v[BB * LL * DD];
__device__ float g_w[BB * HH * LL * LL];       // 134 MB
__device__ float g_attn[BB * LL * DD];
__device__ float g_rs[BB * HH * LL];

// ---------------------------------------------------------------------------
// C[M,N] = A[M,K] @ B[N,K]^T  — 128x128 tile, 256 thr, 8x8 micro, BK=8,
// double-buffered smem + register-staged gmem prefetch.
// ---------------------------------------------------------------------------
__global__ __launch_bounds__(256) void gemm_nt_128(
    const float* __restrict__ A, const float* __restrict__ Bm,
    float* __restrict__ C, int M, int N, int K) {
    __shared__ float As[2][8][132];
    __shared__ float Bs[2][8][132];
    const int tid = threadIdx.x;
    const int tx = tid & 15, ty = tid >> 4;
    const int m0 = blockIdx.y * 128, n0 = blockIdx.x * 128;
    const int lr = tid >> 1, lc = (tid & 1) * 4;
    const float* Ap = A + (size_t)(m0 + lr) * K + lc;
    const float* Bp = Bm + (size_t)(n0 + lr) * K + lc;
    float acc[8][8] = {};
    float4 pa = *(const float4*)Ap;
    float4 pb = *(const float4*)Bp;
    As[0][lc + 0][lr] = pa.x; As[0][lc + 1][lr] = pa.y; As[0][lc + 2][lr] = pa.z; As[0][lc + 3][lr] = pa.w;
    Bs[0][lc + 0][lr] = pb.x; Bs[0][lc + 1][lr] = pb.y; Bs[0][lc + 2][lr] = pb.z; Bs[0][lc + 3][lr] = pb.w;
    __syncthreads();
    const int nit = K >> 3;
    int buf = 0;
    for (int it = 0; it < nit; it++) {
        if (it + 1 < nit) {
            pa = *(const float4*)(Ap + (it + 1) * 8);
            pb = *(const float4*)(Bp + (it + 1) * 8);
        }
#pragma unroll
        for (int kk = 0; kk < 8; kk++) {
            float ar[8], br[8];
            *(float4*)&ar[0] = *(const float4*)&As[buf][kk][ty * 8];
            *(float4*)&ar[4] = *(const float4*)&As[buf][kk][ty * 8 + 4];
            *(float4*)&br[0] = *(const float4*)&Bs[buf][kk][tx * 8];
            *(float4*)&br[4] = *(const float4*)&Bs[buf][kk][tx * 8 + 4];
#pragma unroll
            for (int a = 0; a < 8; a++)
#pragma unroll
                for (int b2 = 0; b2 < 8; b2++)
                    acc[a][b2] += ar[a] * br[b2];
        }
        if (it + 1 < nit) {
            const int nb = buf ^ 1;
            As[nb][lc + 0][lr] = pa.x; As[nb][lc + 1][lr] = pa.y; As[nb][lc + 2][lr] = pa.z; As[nb][lc + 3][lr] = pa.w;
            Bs[nb][lc + 0][lr] = pb.x; Bs[nb][lc + 1][lr] = pb.y; Bs[nb][lc + 2][lr] = pb.z; Bs[nb][lc + 3][lr] = pb.w;
            __syncthreads();
            buf = nb;
        }
    }
#pragma unroll
    for (int a = 0; a < 8; a++) {
        float* cp = C + (size_t)(m0 + ty * 8 + a) * N + n0 + tx * 8;
        *(float4*)cp = make_float4(acc[a][0], acc[a][1], acc[a][2], acc[a][3]);
        *(float4*)(cp + 4) = make_float4(acc[a][4], acc[a][5], acc[a][6], acc[a][7]);
    }
}

// ---------------------------------------------------------------------------
// Toeplitz score:  g_w[bh,l,i] = sum_k q[b,l,h*DH+k] * gen[h,k,(L-1)-l+i]
// 128x128 tile (l x i), sliding-window diagonal trick, double buffered.
// ---------------------------------------------------------------------------
__global__ __launch_bounds__(256) void toeplitz_w(
    const float* __restrict__ q, const float* __restrict__ gen) {
    __shared__ float qs[2][8][132];
    __shared__ float gs[2][8][256];
    const int bh = blockIdx.z, b = bh >> 2, h = bh & 3;
    const int l0 = blockIdx.y * 128, i0 = blockIdx.x * 128;
    const int tid = threadIdx.x;
    const int tx = tid & 15, ty = tid >> 4;
    // q loader
    const int lr = tid >> 1, lc = (tid & 1) * 4;
    const float* Qp = q + (size_t)(b * LL + l0 + lr) * DD + h * DH + lc;
    // gen loader: row gk (0..7), cols gcol..gcol+7
    const int gk = tid >> 5, gcol = (tid & 31) * 8;
    const int cbase = (LL - 1) - l0 - 127 + i0;    // gen col of local window index 0
    const float* genh = gen + (size_t)h * DH * GW;

    float acc[8][8] = {};
    float4 pq = *(const float4*)Qp;
    float pg[8];
#pragma unroll
    for (int j = 0; j < 8; j++) {
        int gc = cbase + gcol + j;
        pg[j] = (gc < GW) ? genh[(size_t)gk * GW + gc] : 0.f;
    }
    qs[0][lc + 0][lr] = pq.x; qs[0][lc + 1][lr] = pq.y; qs[0][lc + 2][lr] = pq.z; qs[0][lc + 3][lr] = pq.w;
#pragma unroll
    for (int j = 0; j < 8; j++) gs[0][gk][gcol + j] = pg[j];
    __syncthreads();

    const int nit = DH / 8;   // 32
    const int gb = 120 - ty * 8 + tx * 8;
    int buf = 0;
    for (int it = 0; it < nit; it++) {
        if (it + 1 < nit) {
            pq = *(const float4*)(Qp + (it + 1) * 8);
#pragma unroll
            for (int j = 0; j < 8; j++) {
                int gc = cbase + gcol + j;
                pg[j] = (gc < GW) ? genh[(size_t)((it + 1) * 8 + gk) * GW + gc] : 0.f;
            }
        }
#pragma unroll
        for (int kk = 0; kk < 8; kk++) {
            float qr[8], gr[16];
            *(float4*)&qr[0] = *(const float4*)&qs[buf][kk][ty * 8];
            *(float4*)&qr[4] = *(const float4*)&qs[buf][kk][ty * 8 + 4];
            *(float4*)&gr[0] = *(const float4*)&gs[buf][kk][gb];
            *(float4*)&gr[4] = *(const float4*)&gs[buf][kk][gb + 4];
            *(float4*)&gr[8] = *(const float4*)&gs[buf][kk][gb + 8];
            *(float4*)&gr[12] = *(const float4*)&gs[buf][kk][gb + 12];
#pragma unroll
            for (int a = 0; a < 8; a++)
#pragma unroll
                for (int b2 = 0; b2 < 8; b2++)
                    acc[a][b2] += qr[a] * gr[7 - a + b2];
        }
        if (it + 1 < nit) {
            const int nb = buf ^ 1;
            qs[nb][lc + 0][lr] = pq.x; qs[nb][lc + 1][lr] = pq.y; qs[nb][lc + 2][lr] = pq.z; qs[nb][lc + 3][lr] = pq.w;
#pragma unroll
            for (int j = 0; j < 8; j++) gs[nb][gk][gcol + j] = pg[j];
            __syncthreads();
            buf = nb;
        }
    }
#pragma unroll
    for (int a = 0; a < 8; a++) {
        float* wp = g_w + (size_t)(bh * LL + l0 + ty * 8 + a) * LL + i0 + tx * 8;
        *(float4*)wp = make_float4(acc[a][0], acc[a][1], acc[a][2], acc[a][3]);
        *(float4*)(wp + 4) = make_float4(acc[a][4], acc[a][5], acc[a][6], acc[a][7]);
    }
}

// ---------------------------------------------------------------------------
// cumsum over l, relu, causal mask (in place). Thread per (bh, i).
// ---------------------------------------------------------------------------
__global__ __launch_bounds__(256) void cumsum_relu_mask() {
    const int bh = blockIdx.y;
    const int i = blockIdx.x * 256 + threadIdx.x;
    float* __restrict__ W = g_w + (size_t)bh * (LL * LL) + i;
    float acc = 0.f;
    for (int l = 0; l < LL; l += 8) {
        float vb[8];
#pragma unroll
        for (int u = 0; u < 8; u++) vb[u] = W[(size_t)(l + u) * LL];
#pragma unroll
        for (int u = 0; u < 8; u++) {
            acc += vb[u];
            W[(size_t)(l + u) * LL] = (i <= l + u) ? fmaxf(acc, 0.f) : 0.f;
        }
    }
}

// ---------------------------------------------------------------------------
// Row sums of masked W.
// ---------------------------------------------------------------------------
__global__ __launch_bounds__(256) void rowsum_k() {
    const int bh = blockIdx.y, l = blockIdx.x;
    const float* __restrict__ W = g_w + (size_t)(bh * LL + l) * LL;
    float s = 0.f;
    for (int i = threadIdx.x; i <= l; i += 256) s += W[i];
#pragma unroll
    for (int o = 16; o > 0; o >>= 1) s += __shfl_xor_sync(0xffffffffu, s, o);
    __shared__ float red[8];
    if ((threadIdx.x & 31) == 0) red[threadIdx.x >> 5] = s;
    __syncthreads();
    if (threadIdx.x < 8) {
        s = red[threadIdx.x];
#pragma unroll
        for (int o = 4; o > 0; o >>= 1) s += __shfl_xor_sync(0xffu, s, o);
        if (threadIdx.x == 0) g_rs[bh * LL + l] = s;
    }
}

// ---------------------------------------------------------------------------
// attn[b,l,h,:] = (1/(rs+1e-8)) * sum_{i<=l} W[bh,l,i] * v[b,i,h,:]
// 128x128 tile over (l x n), K = i (causal bound), double buffered.
// ---------------------------------------------------------------------------
__global__ __launch_bounds__(256) void av_gemm() {
    __shared__ float As[2][8][132];
    __shared__ float Bs[2][8][132];
    const int bh = blockIdx.z, b = bh >> 2, h = bh & 3;
    const int l0 = blockIdx.y * 128, n0 = blockIdx.x * 128;
    const int tid = threadIdx.x;
    const int tx = tid & 15, ty = tid >> 4;
    const int lr = tid >> 1, lc = (tid & 1) * 4;     // A loader (rows l, 8 i-cols)
    const int vk = tid >> 5, vc = (tid & 31) * 4;    // B loader (8 i-rows, 128 n-cols)
    const float* Wp = g_w + (size_t)(bh * LL + l0 + lr) * LL + lc;
    const float* Vp = g_v + (size_t)(b * LL + vk) * DD + h * DH + n0 + vc;
    float acc[8][8] = {};
    float4 pa = *(const float4*)Wp;
    float4 pb = *(const float4*)Vp;
    As[0][lc + 0][lr] = pa.x; As[0][lc + 1][lr] = pa.y; As[0][lc + 2][lr] = pa.z; As[0][lc + 3][lr] = pa.w;
    *(float4*)&Bs[0][vk][vc] = pb;
    __syncthreads();
    const int nit = (l0 + 128) >> 3;
    int buf = 0;
    for (int it = 0; it < nit; it++) {
        if (it + 1 < nit) {
            pa = *(const float4*)(Wp + (it + 1) * 8);
            pb = *(const float4*)(Vp + (size_t)(it + 1) * 8 * DD);
        }
#pragma unroll
        for (int kk = 0; kk < 8; kk++) {
            float ar[8], br[8];
            *(float4*)&ar[0] = *(const float4*)&As[buf][kk][ty * 8];
            *(float4*)&ar[4] = *(const float4*)&As[buf][kk][ty * 8 + 4];
            *(float4*)&br[0] = *(const float4*)&Bs[buf][kk][tx * 8];
            *(float4*)&br[4] = *(const float4*)&Bs[buf][kk][tx * 8 + 4];
#pragma unroll
            for (int a = 0; a < 8; a++)
#pragma unroll
                for (int b2 = 0; b2 < 8; b2++)
                    acc[a][b2] += ar[a] * br[b2];
        }
        if (it + 1 < nit) {
            const int nb = buf ^ 1;
            As[nb][lc + 0][lr] = pa.x; As[nb][lc + 1][lr] = pa.y; As[nb][lc + 2][lr] = pa.z; As[nb][lc + 3][lr] = pa.w;
            *(float4*)&Bs[nb][vk][vc] = pb;
            __syncthreads();
            buf = nb;
        }
    }
#pragma unroll
    for (int a = 0; a < 8; a++) {
        const int row = l0 + ty * 8 + a;
        const float s = 1.f / (g_rs[bh * LL + row] + 1e-8f);
        float* op = g_attn + (size_t)(b * LL + row) * DD + h * DH + n0 + tx * 8;
        *(float4*)op = make_float4(acc[a][0] * s, acc[a][1] * s, acc[a][2] * s, acc[a][3] * s);
        *(float4*)(op + 4) = make_float4(acc[a][4] * s, acc[a][5] * s, acc[a][6] * s, acc[a][7] * s);
    }
}

// ---------------------------------------------------------------------------
extern "C" void kernel_launch(void* const* d_in, const int* in_sizes, int n_in,
                              void* d_out, int out_size) {
    const float* x   = (const float*)d_in[0];
    const float* gen = (const float*)d_in[1];
    const float* Wq  = (const float*)d_in[2];
    const float* Wv  = (const float*)d_in[3];
    const float* Wp  = (const float*)d_in[4];
    float* out = (float*)d_out;

    float *qp, *vp, *ap;
    cudaGetSymbolAddress((void**)&qp, g_q);
    cudaGetSymbolAddress((void**)&vp, g_v);
    cudaGetSymbolAddress((void**)&ap, g_attn);

    const int M = BB * LL;                       // 8192
    dim3 grid_proj(DD / 128, M / 128);           // (8, 64)

    gemm_nt_128<<<grid_proj, 256>>>(x, Wq, qp, M, DD, DD);
    gemm_nt_128<<<grid_proj, 256>>>(x, Wv, vp, M, DD, DD);
    toeplitz_w<<<dim3(LL / 128, LL / 128, BB * HH), 256>>>(qp, gen);
    cumsum_relu_mask<<<dim3(LL / 256, BB * HH), 256>>>();
    rowsum_k<<<dim3(LL, BB * HH), 256>>>();
    av_gemm<<<dim3(DH / 128, LL / 128, BB * HH), 256>>>();
    gemm_nt_128<<<grid_proj, 256>>>(ap, Wp, out, M, DD, DD);
}

// round 7
// speedup vs baseline: 1.1599x; 1.0823x over previous
#include <cuda_runtime.h>

#define BB 8
#define LL 1024
#define DD 1024
#define HH 4
#define DH 256
#define GW 2047

__device__ float g_q[BB * LL * DD];
__device__ float g_v[BB * LL * DD];
__device__ float g_w[BB * HH * LL * LL];
__device__ float g_attn[BB * LL * DD];
__device__ float g_rs[BB * HH * LL];

typedef unsigned long long u64;

__device__ __forceinline__ u64 pk2(float lo, float hi) {
    u64 r; asm("mov.b64 %0, {%1,%2};" : "=l"(r) : "f"(lo), "f"(hi)); return r;
}
__device__ __forceinline__ void fma2(u64& d, u64 a, u64 b) {
    asm("fma.rn.f32x2 %0, %1, %2, %0;" : "+l"(d) : "l"(a), "l"(b));
}
__device__ __forceinline__ float2 upk(u64 v) {
    float2 f; asm("mov.b64 {%0,%1}, %2;" : "=f"(f.x), "=f"(f.y) : "l"(v)); return f;
}

// ---------------------------------------------------------------------------
// C[M,N] = A[M,K] @ B[N,K]^T — 128x128, 256 thr, 8x8 micro (f32x2 packed),
// BK=8, double-buffered smem + register prefetch.
// ---------------------------------------------------------------------------
__global__ __launch_bounds__(256) void gemm_nt_128(
    const float* __restrict__ A, const float* __restrict__ Bm,
    float* __restrict__ C, int M, int N, int K) {
    __shared__ float As[2][8][132];
    __shared__ float Bs[2][8][132];
    const int tid = threadIdx.x;
    const int tx = tid & 15, ty = tid >> 4;
    const int m0 = blockIdx.y * 128, n0 = blockIdx.x * 128;
    const int lr = tid >> 1, lc = (tid & 1) * 4;
    const float* Ap = A + (size_t)(m0 + lr) * K + lc;
    const float* Bp = Bm + (size_t)(n0 + lr) * K + lc;
    u64 accp[8][4];
#pragma unroll
    for (int a = 0; a < 8; a++)
#pragma unroll
        for (int j = 0; j < 4; j++) accp[a][j] = 0ull;
    float4 pa = *(const float4*)Ap;
    float4 pb = *(const float4*)Bp;
    As[0][lc + 0][lr] = pa.x; As[0][lc + 1][lr] = pa.y; As[0][lc + 2][lr] = pa.z; As[0][lc + 3][lr] = pa.w;
    Bs[0][lc + 0][lr] = pb.x; Bs[0][lc + 1][lr] = pb.y; Bs[0][lc + 2][lr] = pb.z; Bs[0][lc + 3][lr] = pb.w;
    __syncthreads();
    const int nit = K >> 3;
    int buf = 0;
    for (int it = 0; it < nit; it++) {
        if (it + 1 < nit) {
            pa = *(const float4*)(Ap + (it + 1) * 8);
            pb = *(const float4*)(Bp + (it + 1) * 8);
        }
#pragma unroll
        for (int kk = 0; kk < 8; kk++) {
            float ar[8];
            *(float4*)&ar[0] = *(const float4*)&As[buf][kk][ty * 8];
            *(float4*)&ar[4] = *(const float4*)&As[buf][kk][ty * 8 + 4];
            u64 brp[4];
            const u64* bq = (const u64*)&Bs[buf][kk][tx * 8];
#pragma unroll
            for (int j = 0; j < 4; j++) brp[j] = bq[j];
#pragma unroll
            for (int a = 0; a < 8; a++) {
                u64 ad = pk2(ar[a], ar[a]);
#pragma unroll
                for (int j = 0; j < 4; j++) fma2(accp[a][j], ad, brp[j]);
            }
        }
        if (it + 1 < nit) {
            const int nb = buf ^ 1;
            As[nb][lc + 0][lr] = pa.x; As[nb][lc + 1][lr] = pa.y; As[nb][lc + 2][lr] = pa.z; As[nb][lc + 3][lr] = pa.w;
            Bs[nb][lc + 0][lr] = pb.x; Bs[nb][lc + 1][lr] = pb.y; Bs[nb][lc + 2][lr] = pb.z; Bs[nb][lc + 3][lr] = pb.w;
            __syncthreads();
            buf = nb;
        }
    }
#pragma unroll
    for (int a = 0; a < 8; a++) {
        float2 p0 = upk(accp[a][0]), p1 = upk(accp[a][1]);
        float2 p2 = upk(accp[a][2]), p3 = upk(accp[a][3]);
        float* cp = C + (size_t)(m0 + ty * 8 + a) * N + n0 + tx * 8;
        *(float4*)cp = make_float4(p0.x, p0.y, p1.x, p1.y);
        *(float4*)(cp + 4) = make_float4(p2.x, p2.y, p3.x, p3.y);
    }
}

// ---------------------------------------------------------------------------
// Toeplitz score:  g_w[bh,l,i] = sum_k q[b,l,h*DH+k] * gen[h,k,(L-1)-l+i]
// 128x128 tile, sliding diagonal window, f32x2 packed, double buffered.
// ---------------------------------------------------------------------------
__global__ __launch_bounds__(256) void toeplitz_w(
    const float* __restrict__ q, const float* __restrict__ gen) {
    __shared__ float qs[2][8][132];
    __shared__ float gs[2][8][256];
    const int bh = blockIdx.z, b = bh >> 2, h = bh & 3;
    const int l0 = blockIdx.y * 128, i0 = blockIdx.x * 128;
    const int tid = threadIdx.x;
    const int tx = tid & 15, ty = tid >> 4;
    const int lr = tid >> 1, lc = (tid & 1) * 4;
    const float* Qp = q + (size_t)(b * LL + l0 + lr) * DD + h * DH + lc;
    const int gk = tid >> 5, gcol = (tid & 31) * 8;
    const int cbase = (LL - 1) - l0 - 127 + i0;
    const float* genh = gen + (size_t)h * DH * GW;

    u64 accp[8][4];
#pragma unroll
    for (int a = 0; a < 8; a++)
#pragma unroll
        for (int j = 0; j < 4; j++) accp[a][j] = 0ull;

    float4 pq = *(const float4*)Qp;
    float pg[8];
#pragma unroll
    for (int j = 0; j < 8; j++) {
        int gc = cbase + gcol + j;
        pg[j] = (gc < GW) ? genh[(size_t)gk * GW + gc] : 0.f;
    }
    qs[0][lc + 0][lr] = pq.x; qs[0][lc + 1][lr] = pq.y; qs[0][lc + 2][lr] = pq.z; qs[0][lc + 3][lr] = pq.w;
#pragma unroll
    for (int j = 0; j < 8; j++) gs[0][gk][gcol + j] = pg[j];
    __syncthreads();

    const int nit = DH / 8;
    const int gb = 120 - ty * 8 + tx * 8;
    int buf = 0;
    for (int it = 0; it < nit; it++) {
        if (it + 1 < nit) {
            pq = *(const float4*)(Qp + (it + 1) * 8);
#pragma unroll
            for (int j = 0; j < 8; j++) {
                int gc = cbase + gcol + j;
                pg[j] = (gc < GW) ? genh[(size_t)((it + 1) * 8 + gk) * GW + gc] : 0.f;
            }
        }
#pragma unroll
        for (int kk = 0; kk < 8; kk++) {
            float qr[8], gr[16];
            *(float4*)&qr[0] = *(const float4*)&qs[buf][kk][ty * 8];
            *(float4*)&qr[4] = *(const float4*)&qs[buf][kk][ty * 8 + 4];
            *(float4*)&gr[0] = *(const float4*)&gs[buf][kk][gb];
            *(float4*)&gr[4] = *(const float4*)&gs[buf][kk][gb + 4];
            *(float4*)&gr[8] = *(const float4*)&gs[buf][kk][gb + 8];
            *(float4*)&gr[12] = *(const float4*)&gs[buf][kk][gb + 12];
            u64 grp[14];
#pragma unroll
            for (int o = 0; o < 14; o++) grp[o] = pk2(gr[o], gr[o + 1]);
#pragma unroll
            for (int a = 0; a < 8; a++) {
                u64 qd = pk2(qr[a], qr[a]);
#pragma unroll
                for (int j = 0; j < 4; j++) fma2(accp[a][j], qd, grp[7 - a + 2 * j]);
            }
        }
        if (it + 1 < nit) {
            const int nb = buf ^ 1;
            qs[nb][lc + 0][lr] = pq.x; qs[nb][lc + 1][lr] = pq.y; qs[nb][lc + 2][lr] = pq.z; qs[nb][lc + 3][lr] = pq.w;
#pragma unroll
            for (int j = 0; j < 8; j++) gs[nb][gk][gcol + j] = pg[j];
            __syncthreads();
            buf = nb;
        }
    }
#pragma unroll
    for (int a = 0; a < 8; a++) {
        float2 p0 = upk(accp[a][0]), p1 = upk(accp[a][1]);
        float2 p2 = upk(accp[a][2]), p3 = upk(accp[a][3]);
        float* wp = g_w + (size_t)(bh * LL + l0 + ty * 8 + a) * LL + i0 + tx * 8;
        *(float4*)wp = make_float4(p0.x, p0.y, p1.x, p1.y);
        *(float4*)(wp + 4) = make_float4(p2.x, p2.y, p3.x, p3.y);
    }
}

// ---------------------------------------------------------------------------
// cumsum over l, relu, causal mask (in place). Unroll 16 for MLP.
// ---------------------------------------------------------------------------
__global__ __launch_bounds__(256) void cumsum_relu_mask() {
    const int bh = blockIdx.y;
    const int i = blockIdx.x * 256 + threadIdx.x;
    float* __restrict__ W = g_w + (size_t)bh * (LL * LL) + i;
    float acc = 0.f;
    for (int l = 0; l < LL; l += 16) {
        float vb[16];
#pragma unroll
        for (int u = 0; u < 16; u++) vb[u] = W[(size_t)(l + u) * LL];
#pragma unroll
        for (int u = 0; u < 16; u++) {
            acc += vb[u];
            W[(size_t)(l + u) * LL] = (i <= l + u) ? fmaxf(acc, 0.f) : 0.f;
        }
    }
}

// ---------------------------------------------------------------------------
__global__ __launch_bounds__(256) void rowsum_k() {
    const int bh = blockIdx.y, l = blockIdx.x;
    const float* __restrict__ W = g_w + (size_t)(bh * LL + l) * LL;
    float s = 0.f;
    for (int i = threadIdx.x; i <= l; i += 256) s += W[i];
#pragma unroll
    for (int o = 16; o > 0; o >>= 1) s += __shfl_xor_sync(0xffffffffu, s, o);
    __shared__ float red[8];
    if ((threadIdx.x & 31) == 0) red[threadIdx.x >> 5] = s;
    __syncthreads();
    if (threadIdx.x < 8) {
        s = red[threadIdx.x];
#pragma unroll
        for (int o = 4; o > 0; o >>= 1) s += __shfl_xor_sync(0xffu, s, o);
        if (threadIdx.x == 0) g_rs[bh * LL + l] = s;
    }
}

// ---------------------------------------------------------------------------
// attn = normalize(W) @ v (causal), f32x2 packed, fused 1/rowsum epilogue.
// ---------------------------------------------------------------------------
__global__ __launch_bounds__(256) void av_gemm() {
    __shared__ float As[2][8][132];
    __shared__ float Bs[2][8][132];
    const int bh = blockIdx.z, b = bh >> 2, h = bh & 3;
    const int l0 = blockIdx.y * 128, n0 = blockIdx.x * 128;
    const int tid = threadIdx.x;
    const int tx = tid & 15, ty = tid >> 4;
    const int lr = tid >> 1, lc = (tid & 1) * 4;
    const int vk = tid >> 5, vc = (tid & 31) * 4;
    const float* Wp = g_w + (size_t)(bh * LL + l0 + lr) * LL + lc;
    const float* Vp = g_v + (size_t)(b * LL + vk) * DD + h * DH + n0 + vc;
    u64 accp[8][4];
#pragma unroll
    for (int a = 0; a < 8; a++)
#pragma unroll
        for (int j = 0; j < 4; j++) accp[a][j] = 0ull;
    float4 pa = *(const float4*)Wp;
    float4 pb = *(const float4*)Vp;
    As[0][lc + 0][lr] = pa.x; As[0][lc + 1][lr] = pa.y; As[0][lc + 2][lr] = pa.z; As[0][lc + 3][lr] = pa.w;
    *(float4*)&Bs[0][vk][vc] = pb;
    __syncthreads();
    const int nit = (l0 + 128) >> 3;
    int buf = 0;
    for (int it = 0; it < nit; it++) {
        if (it + 1 < nit) {
            pa = *(const float4*)(Wp + (it + 1) * 8);
            pb = *(const float4*)(Vp + (size_t)(it + 1) * 8 * DD);
        }
#pragma unroll
        for (int kk = 0; kk < 8; kk++) {
            float ar[8];
            *(float4*)&ar[0] = *(const float4*)&As[buf][kk][ty * 8];
            *(float4*)&ar[4] = *(const float4*)&As[buf][kk][ty * 8 + 4];
            u64 brp[4];
            const u64* bq = (const u64*)&Bs[buf][kk][tx * 8];
#pragma unroll
            for (int j = 0; j < 4; j++) brp[j] = bq[j];
#pragma unroll
            for (int a = 0; a < 8; a++) {
                u64 ad = pk2(ar[a], ar[a]);
#pragma unroll
                for (int j = 0; j < 4; j++) fma2(accp[a][j], ad, brp[j]);
            }
        }
        if (it + 1 < nit) {
            const int nb = buf ^ 1;
            As[nb][lc + 0][lr] = pa.x; As[nb][lc + 1][lr] = pa.y; As[nb][lc + 2][lr] = pa.z; As[nb][lc + 3][lr] = pa.w;
            *(float4*)&Bs[nb][vk][vc] = pb;
            __syncthreads();
            buf = nb;
        }
    }
#pragma unroll
    for (int a = 0; a < 8; a++) {
        const int row = l0 + ty * 8 + a;
        const float s = 1.f / (g_rs[bh * LL + row] + 1e-8f);
        float2 p0 = upk(accp[a][0]), p1 = upk(accp[a][1]);
        float2 p2 = upk(accp[a][2]), p3 = upk(accp[a][3]);
        float* op = g_attn + (size_t)(b * LL + row) * DD + h * DH + n0 + tx * 8;
        *(float4*)op = make_float4(p0.x * s, p0.y * s, p1.x * s, p1.y * s);
        *(float4*)(op + 4) = make_float4(p2.x * s, p2.y * s, p3.x * s, p3.y * s);
    }
}

// ---------------------------------------------------------------------------
extern "C" void kernel_launch(void* const* d_in, const int* in_sizes, int n_in,
                              void* d_out, int out_size) {
    const float* x   = (const float*)d_in[0];
    const float* gen = (const float*)d_in[1];
    const float* Wq  = (const float*)d_in[2];
    const float* Wv  = (const float*)d_in[3];
    const float* Wp  = (const float*)d_in[4];
    float* out = (float*)d_out;

    float *qp, *vp, *ap;
    cudaGetSymbolAddress((void**)&qp, g_q);
    cudaGetSymbolAddress((void**)&vp, g_v);
    cudaGetSymbolAddress((void**)&ap, g_attn);

    const int M = BB * LL;
    dim3 grid_proj(DD / 128, M / 128);

    gemm_nt_128<<<grid_proj, 256>>>(x, Wq, qp, M, DD, DD);
    gemm_nt_128<<<grid_proj, 256>>>(x, Wv, vp, M, DD, DD);
    toeplitz_w<<<dim3(LL / 128, LL / 128, BB * HH), 256>>>(qp, gen);
    cumsum_relu_mask<<<dim3(LL / 256, BB * HH), 256>>>();
    rowsum_k<<<dim3(LL, BB * HH), 256>>>();
    av_gemm<<<dim3(DH / 128, LL / 128, BB * HH), 256>>>();
    gemm_nt_128<<<grid_proj, 256>>>(ap, Wp, out, M, DD, DD);
}

// round 8
// speedup vs baseline: 2.0055x; 1.7291x over previous
#include <cuda_runtime.h>
#include <cuda_bf16.h>

#define BB 8
#define LL 1024
#define DD 1024
#define HH 4
#define DH 256
#define GW 2047
#define GP 2048

typedef unsigned int u32;

// ---------------- device scratch (no allocs allowed) ----------------
__device__ __nv_bfloat16 g_xh[BB*LL*DD], g_xl[BB*LL*DD];
__device__ __nv_bfloat16 g_wqh[DD*DD], g_wql[DD*DD];
__device__ __nv_bfloat16 g_wvh[DD*DD], g_wvl[DD*DD];
__device__ __nv_bfloat16 g_wph[DD*DD], g_wpl[DD*DD];
__device__ __nv_bfloat16 g_gh[HH*DH*GP], g_gl[HH*DH*GP];
__device__ __nv_bfloat16 g_qh[BB*LL*DD], g_ql[BB*LL*DD];
__device__ __nv_bfloat16 g_vh[BB*LL*DD], g_vl[BB*LL*DD];
__device__ __nv_bfloat16 g_ath[BB*LL*DD], g_atl[BB*LL*DD];
__device__ float g_wfull[(size_t)BB*HH*LL*GP];                 // 268 MB
__device__ __nv_bfloat16 g_Wh[(size_t)BB*HH*LL*LL], g_Wl[(size_t)BB*HH*LL*LL];
__device__ float g_rs[BB*HH*LL];

// ---------------- helpers ----------------
__device__ __forceinline__ u32 smaddr(const void* p){
    return (u32)__cvta_generic_to_shared(p);
}
__device__ __forceinline__ void ldsm4(u32* r, u32 a){
    asm volatile("ldmatrix.sync.aligned.m8n8.x4.shared.b16 {%0,%1,%2,%3},[%4];"
        :"=r"(r[0]),"=r"(r[1]),"=r"(r[2]),"=r"(r[3]):"r"(a));
}
__device__ __forceinline__ void ldsm4t(u32* r, u32 a){
    asm volatile("ldmatrix.sync.aligned.m8n8.x4.trans.shared.b16 {%0,%1,%2,%3},[%4];"
        :"=r"(r[0]),"=r"(r[1]),"=r"(r[2]),"=r"(r[3]):"r"(a));
}
__device__ __forceinline__ void mma_bf16(float* c, const u32* a, const u32* b){
    asm volatile("mma.sync.aligned.m16n8k16.row.col.f32.bf16.bf16.f32 "
        "{%0,%1,%2,%3},{%4,%5,%6,%7},{%8,%9},{%0,%1,%2,%3};"
        :"+f"(c[0]),"+f"(c[1]),"+f"(c[2]),"+f"(c[3])
        :"r"(a[0]),"r"(a[1]),"r"(a[2]),"r"(a[3]),"r"(b[0]),"r"(b[1]));
}
__device__ __forceinline__ void st_pair(__nv_bfloat16* H, __nv_bfloat16* L,
                                        size_t off, float v0, float v1){
    __nv_bfloat16 h0=__float2bfloat16(v0), h1=__float2bfloat16(v1);
    __nv_bfloat162 hh; hh.x=h0; hh.y=h1;
    __nv_bfloat162 ll;
    ll.x=__float2bfloat16(v0-__bfloat162float(h0));
    ll.y=__float2bfloat16(v1-__bfloat162float(h1));
    *(__nv_bfloat162*)(H+off)=hh; *(__nv_bfloat162*)(L+off)=ll;
}

// ---------------- fp32 -> bf16 hi/lo converts ----------------
__global__ void conv_pair(const float* __restrict__ in, __nv_bfloat16* __restrict__ hi,
                          __nv_bfloat16* __restrict__ lo, int n){
    int i = blockIdx.x*256 + threadIdx.x;
    if (i < n){
        float v = in[i];
        __nv_bfloat16 h = __float2bfloat16(v);
        hi[i]=h; lo[i]=__float2bfloat16(v-__bfloat162float(h));
    }
}
__global__ void conv_gen_k(const float* __restrict__ gen){
    int idx = blockIdx.x*256 + threadIdx.x;   // over HH*DH*GP
    int j = idx & (GP-1);
    int r = idx >> 11;
    float v = (j < GW) ? gen[(size_t)r*GW + j] : 0.f;
    __nv_bfloat16 h=__float2bfloat16(v);
    g_gh[idx]=h; g_gl[idx]=__float2bfloat16(v-__bfloat162float(h));
}

// ---------------------------------------------------------------------------
// NT GEMM: C[M,N] = A[M,K] @ B[N,K]^T, bf16x3 pairs, 128x128 block, 8 warps.
// emitPair=1 -> write bf16 hi/lo to Chg/Clg; else fp32 to Cf.
// ---------------------------------------------------------------------------
__global__ __launch_bounds__(256) void mma_nt(
    const __nv_bfloat16* __restrict__ Ahg, const __nv_bfloat16* __restrict__ Alg,
    const __nv_bfloat16* __restrict__ Bhg, const __nv_bfloat16* __restrict__ Blg,
    float* __restrict__ Cf, __nv_bfloat16* __restrict__ Chg, __nv_bfloat16* __restrict__ Clg,
    int K, int N, int emitPair)
{
    __shared__ __align__(16) __nv_bfloat16 Ah[2][128][24], Al[2][128][24];
    __shared__ __align__(16) __nv_bfloat16 Bh[2][128][24], Bl[2][128][24];
    const int tid=threadIdx.x, lane=tid&31, wid=tid>>5, wm=wid>>1, wn=wid&1;
    const int m0=blockIdx.y*128, n0=blockIdx.x*128;
    const int lr=tid>>1, lc=(tid&1)<<3;
    const __nv_bfloat16* Ahp=Ahg+(size_t)(m0+lr)*K+lc;
    const __nv_bfloat16* Alp=Alg+(size_t)(m0+lr)*K+lc;
    const __nv_bfloat16* Bhp=Bhg+(size_t)(n0+lr)*K+lc;
    const __nv_bfloat16* Blp=Blg+(size_t)(n0+lr)*K+lc;
    float acc[2][8][4];
#pragma unroll
    for(int i=0;i<2;i++)
#pragma unroll
    for(int j=0;j<8;j++)
#pragma unroll
    for(int k2=0;k2<4;k2++) acc[i][j][k2]=0.f;

    uint4 pah=*(const uint4*)Ahp, pal=*(const uint4*)Alp;
    uint4 pbh=*(const uint4*)Bhp, pbl=*(const uint4*)Blp;
    *(uint4*)&Ah[0][lr][lc]=pah; *(uint4*)&Al[0][lr][lc]=pal;
    *(uint4*)&Bh[0][lr][lc]=pbh; *(uint4*)&Bl[0][lr][lc]=pbl;
    __syncthreads();

    const int nst=K>>4;
    int buf=0;
    const int g=lane>>3;
    const int arow=((g&1)<<3)+(lane&7), acol=(g>>1)<<3;      // A x4 groups
    const int brow=((g>>1)<<3)+(lane&7), bcol=(g&1)<<3;      // B x4 groups (n16 x k16)
    for(int it=0;it<nst;it++){
        if(it+1<nst){
            pah=*(const uint4*)(Ahp+(it+1)*16); pal=*(const uint4*)(Alp+(it+1)*16);
            pbh=*(const uint4*)(Bhp+(it+1)*16); pbl=*(const uint4*)(Blp+(it+1)*16);
        }
        u32 afh[2][4], afl[2][4];
#pragma unroll
        for(int mt=0;mt<2;mt++){
            ldsm4(afh[mt], smaddr(&Ah[buf][wm*32+mt*16+arow][acol]));
            ldsm4(afl[mt], smaddr(&Al[buf][wm*32+mt*16+arow][acol]));
        }
        u32 bfh[4][4], bfl[4][4];
#pragma unroll
        for(int np=0;np<4;np++){
            int nb=wn*64+np*16;
            ldsm4(bfh[np], smaddr(&Bh[buf][nb+brow][bcol]));
            ldsm4(bfl[np], smaddr(&Bl[buf][nb+brow][bcol]));
        }
#pragma unroll
        for(int mt=0;mt<2;mt++)
#pragma unroll
        for(int np=0;np<4;np++)
#pragma unroll
        for(int hf=0;hf<2;hf++){
            int nt=np*2+hf;
            mma_bf16(acc[mt][nt], afh[mt], &bfh[np][hf*2]);
            mma_bf16(acc[mt][nt], afh[mt], &bfl[np][hf*2]);
            mma_bf16(acc[mt][nt], afl[mt], &bfh[np][hf*2]);
        }
        if(it+1<nst){
            buf^=1;
            *(uint4*)&Ah[buf][lr][lc]=pah; *(uint4*)&Al[buf][lr][lc]=pal;
            *(uint4*)&Bh[buf][lr][lc]=pbh; *(uint4*)&Bl[buf][lr][lc]=pbl;
            __syncthreads();
        }
    }
#pragma unroll
    for(int mt=0;mt<2;mt++)
#pragma unroll
    for(int nt=0;nt<8;nt++){
        int r=m0+wm*32+mt*16+(lane>>2);
        int c=n0+wn*64+nt*8+((lane&3)<<1);
        float* a4=acc[mt][nt];
        if(emitPair){
            st_pair(Chg,Clg,(size_t)r*N+c,a4[0],a4[1]);
            st_pair(Chg,Clg,(size_t)(r+8)*N+c,a4[2],a4[3]);
        } else {
            *(float2*)(Cf+(size_t)r*N+c)=make_float2(a4[0],a4[1]);
            *(float2*)(Cf+(size_t)(r+8)*N+c)=make_float2(a4[2],a4[3]);
        }
    }
}

// ---------------------------------------------------------------------------
// Score GEMM: wfull[bh,l,j] = sum_k q[b,l,h*DH+k] * gen[h,k,j], j in [0,2048)
// A = q pair (row stride DD), B = gen pair [k][j] rows (trans ldmatrix).
// ---------------------------------------------------------------------------
__global__ __launch_bounds__(256) void mma_score(){
    __shared__ __align__(16) __nv_bfloat16 Ah[2][128][24], Al[2][128][24];
    __shared__ __align__(16) __nv_bfloat16 Bh[2][16][136], Bl[2][16][136];
    const int tid=threadIdx.x, lane=tid&31, wid=tid>>5, wm=wid>>1, wn=wid&1;
    const int bh=blockIdx.z, b=bh>>2, h=bh&3;
    const int l0=blockIdx.y*128, j0=blockIdx.x*128;
    const int lr=tid>>1, lc=(tid&1)<<3;
    const __nv_bfloat16* Ahp=g_qh+(size_t)(b*LL+l0+lr)*DD+h*DH+lc;
    const __nv_bfloat16* Alp=g_ql+(size_t)(b*LL+l0+lr)*DD+h*DH+lc;
    const int vbr=tid>>4, vbc=(tid&15)<<3;
    const __nv_bfloat16* Bhp=g_gh+(size_t)(h*DH+vbr)*GP+j0+vbc;
    const __nv_bfloat16* Blp=g_gl+(size_t)(h*DH+vbr)*GP+j0+vbc;
    float acc[2][8][4];
#pragma unroll
    for(int i=0;i<2;i++)
#pragma unroll
    for(int j=0;j<8;j++)
#pragma unroll
    for(int k2=0;k2<4;k2++) acc[i][j][k2]=0.f;

    uint4 pah=*(const uint4*)Ahp, pal=*(const uint4*)Alp;
    uint4 pbh=*(const uint4*)Bhp, pbl=*(const uint4*)Blp;
    *(uint4*)&Ah[0][lr][lc]=pah; *(uint4*)&Al[0][lr][lc]=pal;
    *(uint4*)&Bh[0][vbr][vbc]=pbh; *(uint4*)&Bl[0][vbr][vbc]=pbl;
    __syncthreads();

    const int nst=DH>>4;   // 16
    int buf=0;
    const int g=lane>>3;
    const int arow=((g&1)<<3)+(lane&7), acol=(g>>1)<<3;
    const int tbrow=((g&1)<<3)+(lane&7), tbcoff=(g>>1)<<3;   // trans groups
    for(int it=0;it<nst;it++){
        if(it+1<nst){
            pah=*(const uint4*)(Ahp+(it+1)*16); pal=*(const uint4*)(Alp+(it+1)*16);
            pbh=*(const uint4*)(Bhp+(size_t)(it+1)*16*GP);
            pbl=*(const uint4*)(Blp+(size_t)(it+1)*16*GP);
        }
        u32 afh[2][4], afl[2][4];
#pragma unroll
        for(int mt=0;mt<2;mt++){
            ldsm4(afh[mt], smaddr(&Ah[buf][wm*32+mt*16+arow][acol]));
            ldsm4(afl[mt], smaddr(&Al[buf][wm*32+mt*16+arow][acol]));
        }
        u32 bfh[4][4], bfl[4][4];
#pragma unroll
        for(int np=0;np<4;np++){
            int nb=wn*64+np*16;
            ldsm4t(bfh[np], smaddr(&Bh[buf][tbrow][nb+tbcoff]));
            ldsm4t(bfl[np], smaddr(&Bl[buf][tbrow][nb+tbcoff]));
        }
#pragma unroll
        for(int mt=0;mt<2;mt++)
#pragma unroll
        for(int np=0;np<4;np++)
#pragma unroll
        for(int hf=0;hf<2;hf++){
            int nt=np*2+hf;
            mma_bf16(acc[mt][nt], afh[mt], &bfh[np][hf*2]);
            mma_bf16(acc[mt][nt], afh[mt], &bfl[np][hf*2]);
            mma_bf16(acc[mt][nt], afl[mt], &bfh[np][hf*2]);
        }
        if(it+1<nst){
            buf^=1;
            *(uint4*)&Ah[buf][lr][lc]=pah; *(uint4*)&Al[buf][lr][lc]=pal;
            *(uint4*)&Bh[buf][vbr][vbc]=pbh; *(uint4*)&Bl[buf][vbr][vbc]=pbl;
            __syncthreads();
        }
    }
    float* dst=g_wfull+(size_t)bh*LL*GP;
#pragma unroll
    for(int mt=0;mt<2;mt++)
#pragma unroll
    for(int nt=0;nt<8;nt++){
        int r=l0+wm*32+mt*16+(lane>>2);
        int c=j0+wn*64+nt*8+((lane&3)<<1);
        float* a4=acc[mt][nt];
        *(float2*)(dst+(size_t)r*GP+c)=make_float2(a4[0],a4[1]);
        *(float2*)(dst+(size_t)(r+8)*GP+c)=make_float2(a4[2],a4[3]);
    }
}

// ---------------------------------------------------------------------------
// Fused Toeplitz gather + cumsum + relu + mask; emits W as bf16 hi/lo pair.
// out W[bh,l,i] = mask(relu(sum_{l'<=l} wfull[bh,l',1023-l'+i]))
// ---------------------------------------------------------------------------
__global__ __launch_bounds__(256) void cumsum_fuse(){
    const int bh=blockIdx.y;
    const int i=blockIdx.x*256+threadIdx.x;
    const float* src=g_wfull+(size_t)bh*LL*GP+1023+i;     // + l*2047 per step
    __nv_bfloat16* wh=g_Wh+(size_t)bh*LL*LL+i;
    __nv_bfloat16* wl=g_Wl+(size_t)bh*LL*LL+i;
    float acc=0.f;
    for(int l=0;l<LL;l+=8){
        float vb[8];
#pragma unroll
        for(int u=0;u<8;u++) vb[u]=src[(size_t)(l+u)*2047];
#pragma unroll
        for(int u=0;u<8;u++){
            acc+=vb[u];
            float m=(i<=l+u)?fmaxf(acc,0.f):0.f;
            __nv_bfloat16 hh=__float2bfloat16(m);
            wh[(size_t)(l+u)*LL]=hh;
            wl[(size_t)(l+u)*LL]=__float2bfloat16(m-__bfloat162float(hh));
        }
    }
}

// ---------------------------------------------------------------------------
__global__ __launch_bounds__(256) void rowsum_k(){
    const int bh=blockIdx.y, l=blockIdx.x;
    const __nv_bfloat16* wh=g_Wh+(size_t)(bh*LL+l)*LL;
    const __nv_bfloat16* wl=g_Wl+(size_t)(bh*LL+l)*LL;
    float s=0.f;
    for(int i=threadIdx.x;i<=l;i+=256)
        s+=__bfloat162float(wh[i])+__bfloat162float(wl[i]);
#pragma unroll
    for(int o=16;o>0;o>>=1) s+=__shfl_xor_sync(0xffffffffu,s,o);
    __shared__ float red[8];
    if((threadIdx.x&31)==0) red[threadIdx.x>>5]=s;
    __syncthreads();
    if(threadIdx.x<8){
        s=red[threadIdx.x];
#pragma unroll
        for(int o=4;o>0;o>>=1) s+=__shfl_xor_sync(0xffu,s,o);
        if(threadIdx.x==0) g_rs[bh*LL+l]=s;
    }
}

// ---------------------------------------------------------------------------
// AV GEMM: attn[b,l,h,n] = (1/(rs+1e-8)) * sum_i W[bh,l,i] * v[b,i,h,n]
// A = W pair (k=i contiguous), B = v pair [i][n] rows (trans), causal K bound.
// ---------------------------------------------------------------------------
__global__ __launch_bounds__(256) void mma_av(){
    __shared__ __align__(16) __nv_bfloat16 Ah[2][128][24], Al[2][128][24];
    __shared__ __align__(16) __nv_bfloat16 Bh[2][16][136], Bl[2][16][136];
    const int tid=threadIdx.x, lane=tid&31, wid=tid>>5, wm=wid>>1, wn=wid&1;
    const int bh=blockIdx.z, b=bh>>2, h=bh&3;
    const int l0=blockIdx.y*128, n0=blockIdx.x*128;
    const int lr=tid>>1, lc=(tid&1)<<3;
    const __nv_bfloat16* Ahp=g_Wh+(size_t)(bh*LL+l0+lr)*LL+lc;
    const __nv_bfloat16* Alp=g_Wl+(size_t)(bh*LL+l0+lr)*LL+lc;
    const int vbr=tid>>4, vbc=(tid&15)<<3;
    const __nv_bfloat16* Bhp=g_vh+(size_t)(b*LL+vbr)*DD+h*DH+n0+vbc;
    const __nv_bfloat16* Blp=g_vl+(size_t)(b*LL+vbr)*DD+h*DH+n0+vbc;
    float acc[2][8][4];
#pragma unroll
    for(int i=0;i<2;i++)
#pragma unroll
    for(int j=0;j<8;j++)
#pragma unroll
    for(int k2=0;k2<4;k2++) acc[i][j][k2]=0.f;

    uint4 pah=*(const uint4*)Ahp, pal=*(const uint4*)Alp;
    uint4 pbh=*(const uint4*)Bhp, pbl=*(const uint4*)Blp;
    *(uint4*)&Ah[0][lr][lc]=pah; *(uint4*)&Al[0][lr][lc]=pal;
    *(uint4*)&Bh[0][vbr][vbc]=pbh; *(uint4*)&Bl[0][vbr][vbc]=pbl;
    __syncthreads();

    const int nst=(l0+128)>>4;
    int buf=0;
    const int g=lane>>3;
    const int arow=((g&1)<<3)+(lane&7), acol=(g>>1)<<3;
    const int tbrow=((g&1)<<3)+(lane&7), tbcoff=(g>>1)<<3;
    for(int it=0;it<nst;it++){
        if(it+1<nst){
            pah=*(const uint4*)(Ahp+(it+1)*16); pal=*(const uint4*)(Alp+(it+1)*16);
            pbh=*(const uint4*)(Bhp+(size_t)(it+1)*16*DD);
            pbl=*(const uint4*)(Blp+(size_t)(it+1)*16*DD);
        }
        u32 afh[2][4], afl[2][4];
#pragma unroll
        for(int mt=0;mt<2;mt++){
            ldsm4(afh[mt], smaddr(&Ah[buf][wm*32+mt*16+arow][acol]));
            ldsm4(afl[mt], smaddr(&Al[buf][wm*32+mt*16+arow][acol]));
        }
        u32 bfh[4][4], bfl[4][4];
#pragma unroll
        for(int np=0;np<4;np++){
            int nb=wn*64+np*16;
            ldsm4t(bfh[np], smaddr(&Bh[buf][tbrow][nb+tbcoff]));
            ldsm4t(bfl[np], smaddr(&Bl[buf][tbrow][nb+tbcoff]));
        }
#pragma unroll
        for(int mt=0;mt<2;mt++)
#pragma unroll
        for(int np=0;np<4;np++)
#pragma unroll
        for(int hf=0;hf<2;hf++){
            int nt=np*2+hf;
            mma_bf16(acc[mt][nt], afh[mt], &bfh[np][hf*2]);
            mma_bf16(acc[mt][nt], afh[mt], &bfl[np][hf*2]);
            mma_bf16(acc[mt][nt], afl[mt], &bfh[np][hf*2]);
        }
        if(it+1<nst){
            buf^=1;
            *(uint4*)&Ah[buf][lr][lc]=pah; *(uint4*)&Al[buf][lr][lc]=pal;
            *(uint4*)&Bh[buf][vbr][vbc]=pbh; *(uint4*)&Bl[buf][vbr][vbc]=pbl;
            __syncthreads();
        }
    }
#pragma unroll
    for(int mt=0;mt<2;mt++)
#pragma unroll
    for(int nt=0;nt<8;nt++){
        int r=l0+wm*32+mt*16+(lane>>2);
        int cD=h*DH+n0+wn*64+nt*8+((lane&3)<<1);
        float s0=1.f/(g_rs[bh*LL+r]+1e-8f);
        float s1=1.f/(g_rs[bh*LL+r+8]+1e-8f);
        float* a4=acc[mt][nt];
        st_pair(g_ath,g_atl,(size_t)(b*LL+r)*DD+cD,a4[0]*s0,a4[1]*s0);
        st_pair(g_ath,g_atl,(size_t)(b*LL+r+8)*DD+cD,a4[2]*s1,a4[3]*s1);
    }
}

// ---------------------------------------------------------------------------
extern "C" void kernel_launch(void* const* d_in, const int* in_sizes, int n_in,
                              void* d_out, int out_size) {
    const float* x   = (const float*)d_in[0];
    const float* gen = (const float*)d_in[1];
    const float* Wq  = (const float*)d_in[2];
    const float* Wv  = (const float*)d_in[3];
    const float* Wp  = (const float*)d_in[4];
    float* out = (float*)d_out;

    __nv_bfloat16 *xh,*xl,*wqh,*wql,*wvh,*wvl,*wph,*wpl,*qh,*ql,*vh,*vl,*ath,*atl;
    cudaGetSymbolAddress((void**)&xh,  g_xh);  cudaGetSymbolAddress((void**)&xl,  g_xl);
    cudaGetSymbolAddress((void**)&wqh, g_wqh); cudaGetSymbolAddress((void**)&wql, g_wql);
    cudaGetSymbolAddress((void**)&wvh, g_wvh); cudaGetSymbolAddress((void**)&wvl, g_wvl);
    cudaGetSymbolAddress((void**)&wph, g_wph); cudaGetSymbolAddress((void**)&wpl, g_wpl);
    cudaGetSymbolAddress((void**)&qh,  g_qh);  cudaGetSymbolAddress((void**)&ql,  g_ql);
    cudaGetSymbolAddress((void**)&vh,  g_vh);  cudaGetSymbolAddress((void**)&vl,  g_vl);
    cudaGetSymbolAddress((void**)&ath, g_ath); cudaGetSymbolAddress((void**)&atl, g_atl);

    conv_pair<<<(BB*LL*DD)/256,256>>>(x, xh, xl, BB*LL*DD);
    conv_pair<<<(DD*DD)/256,256>>>(Wq, wqh, wql, DD*DD);
    conv_pair<<<(DD*DD)/256,256>>>(Wv, wvh, wvl, DD*DD);
    conv_pair<<<(DD*DD)/256,256>>>(Wp, wph, wpl, DD*DD);
    conv_gen_k<<<(HH*DH*GP)/256,256>>>(gen);

    mma_nt<<<dim3(DD/128, BB*LL/128),256>>>(xh,xl,wqh,wql,nullptr,qh,ql,DD,DD,1);
    mma_nt<<<dim3(DD/128, BB*LL/128),256>>>(xh,xl,wvh,wvl,nullptr,vh,vl,DD,DD,1);

    mma_score<<<dim3(GP/128, LL/128, BB*HH),256>>>();
    cumsum_fuse<<<dim3(LL/256, BB*HH),256>>>();
    rowsum_k<<<dim3(LL, BB*HH),256>>>();
    mma_av<<<dim3(DH/128, LL/128, BB*HH),256>>>();

    mma_nt<<<dim3(DD/128, BB*LL/128),256>>>(ath,atl,wph,wpl,out,nullptr,nullptr,DD,DD,0);
}

// round 12
// speedup vs baseline: 2.6840x; 1.3383x over previous
#include <cuda_runtime.h>
#include <cuda_fp16.h>

#define BB 8
#define LL 1024
#define DD 1024
#define HH 4
#define DH 256
#define GW 2047
#define GP 2048

typedef unsigned int u32;

// ---------------- device scratch ----------------
__device__ __half g_xh[BB*LL*DD], g_xl[BB*LL*DD];
__device__ __half g_wqh[DD*DD], g_wvh[DD*DD], g_wph[DD*DD];
__device__ __half g_gh[HH*DH*GP];
__device__ __half g_qh[BB*LL*DD], g_ql[BB*LL*DD];
__device__ __half g_vh[BB*LL*DD];
__device__ __half g_ath[BB*LL*DD], g_atl[BB*LL*DD];
__device__ float g_wfull[(size_t)BB*HH*LL*GP];
__device__ __half g_Wh[(size_t)BB*HH*LL*LL], g_Wl[(size_t)BB*HH*LL*LL];
__device__ float g_rs[BB*HH*LL];

// ---------------- helpers ----------------
__device__ __forceinline__ u32 smaddr(const void* p){
    return (u32)__cvta_generic_to_shared(p);
}
__device__ __forceinline__ void ldsm4(u32* r, u32 a){
    asm volatile("ldmatrix.sync.aligned.m8n8.x4.shared.b16 {%0,%1,%2,%3},[%4];"
        :"=r"(r[0]),"=r"(r[1]),"=r"(r[2]),"=r"(r[3]):"r"(a));
}
__device__ __forceinline__ void ldsm4t(u32* r, u32 a){
    asm volatile("ldmatrix.sync.aligned.m8n8.x4.trans.shared.b16 {%0,%1,%2,%3},[%4];"
        :"=r"(r[0]),"=r"(r[1]),"=r"(r[2]),"=r"(r[3]):"r"(a));
}
__device__ __forceinline__ void mma_f16(float* c, const u32* a, const u32* b){
    asm volatile("mma.sync.aligned.m16n8k16.row.col.f32.f16.f16.f32 "
        "{%0,%1,%2,%3},{%4,%5,%6,%7},{%8,%9},{%0,%1,%2,%3};"
        :"+f"(c[0]),"+f"(c[1]),"+f"(c[2]),"+f"(c[3])
        :"r"(a[0]),"r"(a[1]),"r"(a[2]),"r"(a[3]),"r"(b[0]),"r"(b[1]));
}
__device__ __forceinline__ void st_pair(__half* H, __half* L, size_t off, float v0, float v1){
    __half h0=__float2half_rn(v0), h1=__float2half_rn(v1);
    __half2 hh; hh.x=h0; hh.y=h1;
    __half2 ll;
    ll.x=__float2half_rn(v0-__half2float(h0));
    ll.y=__float2half_rn(v1-__half2float(h1));
    *(__half2*)(H+off)=hh; *(__half2*)(L+off)=ll;
}

// ---------------- converts ----------------
__global__ void conv_pair(const float* __restrict__ in, __half* __restrict__ hi,
                          __half* __restrict__ lo, int n){
    int i = blockIdx.x*256 + threadIdx.x;
    if (i < n){
        float v = in[i];
        __half h = __float2half_rn(v);
        hi[i]=h; lo[i]=__float2half_rn(v-__half2float(h));
    }
}
__global__ void conv_hi(const float* __restrict__ in, __half* __restrict__ hi, int n){
    int i = blockIdx.x*256 + threadIdx.x;
    if (i < n) hi[i]=__float2half_rn(in[i]);
}
__global__ void conv_gen_k(const float* __restrict__ gen){
    int idx = blockIdx.x*256 + threadIdx.x;
    int j = idx & (GP-1);
    int r = idx >> 11;
    float v = (j < GW) ? gen[(size_t)r*GW + j] : 0.f;
    g_gh[idx]=__float2half_rn(v);
}

// ---------------------------------------------------------------------------
// NT GEMM: C = A @ B^T. A = fp16 pair, B = fp16 hi. 128x128, 8 warps.
// emit: 0 = fp32 to Cf, 1 = pair to Chg/Clg, 2 = hi-only to Chg.
// ---------------------------------------------------------------------------
__global__ __launch_bounds__(256) void mma_nt(
    const __half* __restrict__ Ahg, const __half* __restrict__ Alg,
    const __half* __restrict__ Bhg,
    float* __restrict__ Cf, __half* __restrict__ Chg, __half* __restrict__ Clg,
    int K, int N, int emit)
{
    __shared__ __align__(16) __half Ah[2][128][24], Al[2][128][24];
    __shared__ __align__(16) __half Bh[2][128][24];
    const int tid=threadIdx.x, lane=tid&31, wid=tid>>5, wm=wid>>1, wn=wid&1;
    const int m0=blockIdx.y*128, n0=blockIdx.x*128;
    const int lr=tid>>1, lc=(tid&1)<<3;
    const __half* Ahp=Ahg+(size_t)(m0+lr)*K+lc;
    const __half* Alp=Alg+(size_t)(m0+lr)*K+lc;
    const __half* Bhp=Bhg+(size_t)(n0+lr)*K+lc;
    float acc[2][8][4];
#pragma unroll
    for(int i=0;i<2;i++)
#pragma unroll
    for(int j=0;j<8;j++)
#pragma unroll
    for(int k2=0;k2<4;k2++) acc[i][j][k2]=0.f;

    uint4 pah=*(const uint4*)Ahp, pal=*(const uint4*)Alp, pbh=*(const uint4*)Bhp;
    *(uint4*)&Ah[0][lr][lc]=pah; *(uint4*)&Al[0][lr][lc]=pal;
    *(uint4*)&Bh[0][lr][lc]=pbh;
    __syncthreads();

    const int nst=K>>4;
    int buf=0;
    const int g=lane>>3;
    const int arow=((g&1)<<3)+(lane&7), acol=(g>>1)<<3;
    const int brow=((g>>1)<<3)+(lane&7), bcol=(g&1)<<3;
    for(int it=0;it<nst;it++){
        if(it+1<nst){
            pah=*(const uint4*)(Ahp+(it+1)*16); pal=*(const uint4*)(Alp+(it+1)*16);
            pbh=*(const uint4*)(Bhp+(it+1)*16);
        }
        u32 afh[2][4], afl[2][4];
#pragma unroll
        for(int mt=0;mt<2;mt++){
            ldsm4(afh[mt], smaddr(&Ah[buf][wm*32+mt*16+arow][acol]));
            ldsm4(afl[mt], smaddr(&Al[buf][wm*32+mt*16+arow][acol]));
        }
        u32 bfh[4][4];
#pragma unroll
        for(int np=0;np<4;np++)
            ldsm4(bfh[np], smaddr(&Bh[buf][wn*64+np*16+brow][bcol]));
#pragma unroll
        for(int mt=0;mt<2;mt++)
#pragma unroll
        for(int np=0;np<4;np++)
#pragma unroll
        for(int hf=0;hf<2;hf++){
            int nt=np*2+hf;
            mma_f16(acc[mt][nt], afh[mt], &bfh[np][hf*2]);
            mma_f16(acc[mt][nt], afl[mt], &bfh[np][hf*2]);
        }
        if(it+1<nst){
            buf^=1;
            *(uint4*)&Ah[buf][lr][lc]=pah; *(uint4*)&Al[buf][lr][lc]=pal;
            *(uint4*)&Bh[buf][lr][lc]=pbh;
            __syncthreads();
        }
    }
#pragma unroll
    for(int mt=0;mt<2;mt++)
#pragma unroll
    for(int nt=0;nt<8;nt++){
        int r=m0+wm*32+mt*16+(lane>>2);
        int c=n0+wn*64+nt*8+((lane&3)<<1);
        float* a4=acc[mt][nt];
        if(emit==1){
            st_pair(Chg,Clg,(size_t)r*N+c,a4[0],a4[1]);
            st_pair(Chg,Clg,(size_t)(r+8)*N+c,a4[2],a4[3]);
        } else if(emit==2){
            __half2 h0; h0.x=__float2half_rn(a4[0]); h0.y=__float2half_rn(a4[1]);
            __half2 h1; h1.x=__float2half_rn(a4[2]); h1.y=__float2half_rn(a4[3]);
            *(__half2*)(Chg+(size_t)r*N+c)=h0;
            *(__half2*)(Chg+(size_t)(r+8)*N+c)=h1;
        } else {
            *(float2*)(Cf+(size_t)r*N+c)=make_float2(a4[0],a4[1]);
            *(float2*)(Cf+(size_t)(r+8)*N+c)=make_float2(a4[2],a4[3]);
        }
    }
}

// ---------------------------------------------------------------------------
// Score GEMM: wfull[bh,l,j] = sum_k q[b,l,h*DH+k] * gen[h,k,j]
// Band restriction: tile used iff 769 <= l0+j0 <= 2046.
// ---------------------------------------------------------------------------
__global__ __launch_bounds__(256) void mma_score(){
    const int l0=blockIdx.y*128, j0=blockIdx.x*128;
    if (l0 + j0 < 769 || l0 + j0 > 2046) return;
    __shared__ __align__(16) __half Ah[2][128][24], Al[2][128][24];
    __shared__ __align__(16) __half Bh[2][16][136];
    const int tid=threadIdx.x, lane=tid&31, wid=tid>>5, wm=wid>>1, wn=wid&1;
    const int bh=blockIdx.z, b=bh>>2, h=bh&3;
    const int lr=tid>>1, lc=(tid&1)<<3;
    const __half* Ahp=g_qh+(size_t)(b*LL+l0+lr)*DD+h*DH+lc;
    const __half* Alp=g_ql+(size_t)(b*LL+l0+lr)*DD+h*DH+lc;
    const int vbr=tid>>4, vbc=(tid&15)<<3;
    const __half* Bhp=g_gh+(size_t)(h*DH+vbr)*GP+j0+vbc;
    float acc[2][8][4];
#pragma unroll
    for(int i=0;i<2;i++)
#pragma unroll
    for(int j=0;j<8;j++)
#pragma unroll
    for(int k2=0;k2<4;k2++) acc[i][j][k2]=0.f;

    uint4 pah=*(const uint4*)Ahp, pal=*(const uint4*)Alp, pbh=*(const uint4*)Bhp;
    *(uint4*)&Ah[0][lr][lc]=pah; *(uint4*)&Al[0][lr][lc]=pal;
    *(uint4*)&Bh[0][vbr][vbc]=pbh;
    __syncthreads();

    const int nst=DH>>4;
    int buf=0;
    const int g=lane>>3;
    const int arow=((g&1)<<3)+(lane&7), acol=(g>>1)<<3;
    const int tbrow=((g&1)<<3)+(lane&7), tbcoff=(g>>1)<<3;
    for(int it=0;it<nst;it++){
        if(it+1<nst){
            pah=*(const uint4*)(Ahp+(it+1)*16); pal=*(const uint4*)(Alp+(it+1)*16);
            pbh=*(const uint4*)(Bhp+(size_t)(it+1)*16*GP);
        }
        u32 afh[2][4], afl[2][4];
#pragma unroll
        for(int mt=0;mt<2;mt++){
            ldsm4(afh[mt], smaddr(&Ah[buf][wm*32+mt*16+arow][acol]));
            ldsm4(afl[mt], smaddr(&Al[buf][wm*32+mt*16+arow][acol]));
        }
        u32 bfh[4][4];
#pragma unroll
        for(int np=0;np<4;np++)
            ldsm4t(bfh[np], smaddr(&Bh[buf][tbrow][wn*64+np*16+tbcoff]));
#pragma unroll
        for(int mt=0;mt<2;mt++)
#pragma unroll
        for(int np=0;np<4;np++)
#pragma unroll
        for(int hf=0;hf<2;hf++){
            int nt=np*2+hf;
            mma_f16(acc[mt][nt], afh[mt], &bfh[np][hf*2]);
            mma_f16(acc[mt][nt], afl[mt], &bfh[np][hf*2]);
        }
        if(it+1<nst){
            buf^=1;
            *(uint4*)&Ah[buf][lr][lc]=pah; *(uint4*)&Al[buf][lr][lc]=pal;
            *(uint4*)&Bh[buf][vbr][vbc]=pbh;
            __syncthreads();
        }
    }
    float* dst=g_wfull+(size_t)bh*LL*GP;
#pragma unroll
    for(int mt=0;mt<2;mt++)
#pragma unroll
    for(int nt=0;nt<8;nt++){
        int r=l0+wm*32+mt*16+(lane>>2);
        int c=j0+wn*64+nt*8+((lane&3)<<1);
        float* a4=acc[mt][nt];
        *(float2*)(dst+(size_t)r*GP+c)=make_float2(a4[0],a4[1]);
        *(float2*)(dst+(size_t)(r+8)*GP+c)=make_float2(a4[2],a4[3]);
    }
}

// ---------------------------------------------------------------------------
// Fused Toeplitz gather + cumsum + relu + mask; W emitted as fp16 pair.
// ---------------------------------------------------------------------------
__global__ __launch_bounds__(256) void cumsum_fuse(){
    const int bh=blockIdx.y;
    const int i=blockIdx.x*256+threadIdx.x;
    const float* src=g_wfull+(size_t)bh*LL*GP+1023+i;
    __half* wh=g_Wh+(size_t)bh*LL*LL+i;
    __half* wl=g_Wl+(size_t)bh*LL*LL+i;
    float acc=0.f;
    for(int l=0;l<LL;l+=8){
        float vb[8];
#pragma unroll
        for(int u=0;u<8;u++) vb[u]=src[(size_t)(l+u)*2047];
#pragma unroll
        for(int u=0;u<8;u++){
            acc+=vb[u];
            float m=(i<=l+u)?fmaxf(acc,0.f):0.f;
            __half hh=__float2half_rn(m);
            wh[(size_t)(l+u)*LL]=hh;
            wl[(size_t)(l+u)*LL]=__float2half_rn(m-__half2float(hh));
        }
    }
}

// ---------------------------------------------------------------------------
__global__ __launch_bounds__(256) void rowsum_k(){
    const int bh=blockIdx.y, l=blockIdx.x;
    const __half* wh=g_Wh+(size_t)(bh*LL+l)*LL;
    const __half* wl=g_Wl+(size_t)(bh*LL+l)*LL;
    float s=0.f;
    for(int i=threadIdx.x;i<=l;i+=256)
        s+=__half2float(wh[i])+__half2float(wl[i]);
#pragma unroll
    for(int o=16;o>0;o>>=1) s+=__shfl_xor_sync(0xffffffffu,s,o);
    __shared__ float red[8];
    if((threadIdx.x&31)==0) red[threadIdx.x>>5]=s;
    __syncthreads();
    if(threadIdx.x<8){
        s=red[threadIdx.x];
#pragma unroll
        for(int o=4;o>0;o>>=1) s+=__shfl_xor_sync(0xffu,s,o);
        if(threadIdx.x==0) g_rs[bh*LL+l]=s;
    }
}

// ---------------------------------------------------------------------------
// AV GEMM: attn = normalize(W) @ v (causal). A = W pair, B = v hi (trans).
// ---------------------------------------------------------------------------
__global__ __launch_bounds__(256) void mma_av(){
    __shared__ __align__(16) __half Ah[2][128][24], Al[2][128][24];
    __shared__ __align__(16) __half Bh[2][16][136];
    const int tid=threadIdx.x, lane=tid&31, wid=tid>>5, wm=wid>>1, wn=wid&1;
    const int bh=blockIdx.z, b=bh>>2, h=bh&3;
    const int l0=blockIdx.y*128, n0=blockIdx.x*128;
    const int lr=tid>>1, lc=(tid&1)<<3;
    const __half* Ahp=g_Wh+(size_t)(bh*LL+l0+lr)*LL+lc;
    const __half* Alp=g_Wl+(size_t)(bh*LL+l0+lr)*LL+lc;
    const int vbr=tid>>4, vbc=(tid&15)<<3;
    const __half* Bhp=g_vh+(size_t)(b*LL+vbr)*DD+h*DH+n0+vbc;
    float acc[2][8][4];
#pragma unroll
    for(int i=0;i<2;i++)
#pragma unroll
    for(int j=0;j<8;j++)
#pragma unroll
    for(int k2=0;k2<4;k2++) acc[i][j][k2]=0.f;

    uint4 pah=*(const uint4*)Ahp, pal=*(const uint4*)Alp, pbh=*(const uint4*)Bhp;
    *(uint4*)&Ah[0][lr][lc]=pah; *(uint4*)&Al[0][lr][lc]=pal;
    *(uint4*)&Bh[0][vbr][vbc]=pbh;
    __syncthreads();

    const int nst=(l0+128)>>4;
    int buf=0;
    const int g=lane>>3;
    const int arow=((g&1)<<3)+(lane&7), acol=(g>>1)<<3;
    const int tbrow=((g&1)<<3)+(lane&7), tbcoff=(g>>1)<<3;
    for(int it=0;it<nst;it++){
        if(it+1<nst){
            pah=*(const uint4*)(Ahp+(it+1)*16); pal=*(const uint4*)(Alp+(it+1)*16);
            pbh=*(const uint4*)(Bhp+(size_t)(it+1)*16*DD);
        }
        u32 afh[2][4], afl[2][4];
#pragma unroll
        for(int mt=0;mt<2;mt++){
            ldsm4(afh[mt], smaddr(&Ah[buf][wm*32+mt*16+arow][acol]));
            ldsm4(afl[mt], smaddr(&Al[buf][wm*32+mt*16+arow][acol]));
        }
        u32 bfh[4][4];
#pragma unroll
        for(int np=0;np<4;np++)
            ldsm4t(bfh[np], smaddr(&Bh[buf][tbrow][wn*64+np*16+tbcoff]));
#pragma unroll
        for(int mt=0;mt<2;mt++)
#pragma unroll
        for(int np=0;np<4;np++)
#pragma unroll
        for(int hf=0;hf<2;hf++){
            int nt=np*2+hf;
            mma_f16(acc[mt][nt], afh[mt], &bfh[np][hf*2]);
            mma_f16(acc[mt][nt], afl[mt], &bfh[np][hf*2]);
        }
        if(it+1<nst){
            buf^=1;
            *(uint4*)&Ah[buf][lr][lc]=pah; *(uint4*)&Al[buf][lr][lc]=pal;
            *(uint4*)&Bh[buf][vbr][vbc]=pbh;
            __syncthreads();
        }
    }
#pragma unroll
    for(int mt=0;mt<2;mt++)
#pragma unroll
    for(int nt=0;nt<8;nt++){
        int r=l0+wm*32+mt*16+(lane>>2);
        int cD=h*DH+n0+wn*64+nt*8+((lane&3)<<1);
        float s0=1.f/(g_rs[bh*LL+r]+1e-8f);
        float s1=1.f/(g_rs[bh*LL+r+8]+1e-8f);
        float* a4=acc[mt][nt];
        st_pair(g_ath,g_atl,(size_t)(b*LL+r)*DD+cD,a4[0]*s0,a4[1]*s0);
        st_pair(g_ath,g_atl,(size_t)(b*LL+r+8)*DD+cD,a4[2]*s1,a4[3]*s1);
    }
}

// ---------------------------------------------------------------------------
extern "C" void kernel_launch(void* const* d_in, const int* in_sizes, int n_in,
                              void* d_out, int out_size) {
    const float* x   = (const float*)d_in[0];
    const float* gen = (const float*)d_in[1];
    const float* Wq  = (const float*)d_in[2];
    const float* Wv  = (const float*)d_in[3];
    const float* Wp  = (const float*)d_in[4];
    float* out = (float*)d_out;

    __half *xh,*xl,*wqh,*wvh,*wph,*qh,*ql,*vh,*ath,*atl;
    cudaGetSymbolAddress((void**)&xh,  g_xh);  cudaGetSymbolAddress((void**)&xl,  g_xl);
    cudaGetSymbolAddress((void**)&wqh, g_wqh);
    cudaGetSymbolAddress((void**)&wvh, g_wvh);
    cudaGetSymbolAddress((void**)&wph, g_wph);
    cudaGetSymbolAddress((void**)&qh,  g_qh);  cudaGetSymbolAddress((void**)&ql,  g_ql);
    cudaGetSymbolAddress((void**)&vh,  g_vh);
    cudaGetSymbolAddress((void**)&ath, g_ath); cudaGetSymbolAddress((void**)&atl, g_atl);

    conv_pair<<<(BB*LL*DD)/256,256>>>(x, xh, xl, BB*LL*DD);
    conv_hi<<<(DD*DD)/256,256>>>(Wq, wqh, DD*DD);
    conv_hi<<<(DD*DD)/256,256>>>(Wv, wvh, DD*DD);
    conv_hi<<<(DD*DD)/256,256>>>(Wp, wph, DD*DD);
    conv_gen_k<<<(HH*DH*GP)/256,256>>>(gen);

    mma_nt<<<dim3(DD/128, BB*LL/128),256>>>(xh,xl,wqh,nullptr,qh,ql,DD,DD,1);
    mma_nt<<<dim3(DD/128, BB*LL/128),256>>>(xh,xl,wvh,nullptr,vh,nullptr,DD,DD,2);

    mma_score<<<dim3(GP/128, LL/128, BB*HH),256>>>();
    cumsum_fuse<<<dim3(LL/256, BB*HH),256>>>();
    rowsum_k<<<dim3(LL, BB*HH),256>>>();
    mma_av<<<dim3(DH/128, LL/128, BB*HH),256>>>();

    mma_nt<<<dim3(DD/128, BB*LL/128),256>>>(ath,atl,wph,out,nullptr,nullptr,DD,DD,0);
}

// round 14
// speedup vs baseline: 3.2175x; 1.1988x over previous
#include <cuda_runtime.h>
#include <cuda_fp16.h>

#define BB 8
#define LL 1024
#define DD 1024
#define HH 4
#define DH 256
#define GW 2047
#define GP 2048

typedef unsigned int u32;

// ---------------- device scratch ----------------
__device__ __half g_xh[BB*LL*DD], g_xl[BB*LL*DD];
__device__ __half g_wqh[DD*DD], g_wvh[DD*DD], g_wph[DD*DD];
__device__ __half g_gh[HH*DH*GP];
__device__ __half g_qh[BB*LL*DD], g_ql[BB*LL*DD];
__device__ __half g_vh[BB*LL*DD];
__device__ __half g_ath[BB*LL*DD], g_atl[BB*LL*DD];
__device__ float g_wfull[(size_t)BB*HH*LL*GP];
__device__ __half g_Wh[(size_t)BB*HH*LL*LL], g_Wl[(size_t)BB*HH*LL*LL];
__device__ float g_rs[BB*HH*LL];

// ---------------- helpers ----------------
__device__ __forceinline__ u32 smaddr(const void* p){
    return (u32)__cvta_generic_to_shared(p);
}
__device__ __forceinline__ void ldsm4(u32* r, u32 a){
    asm volatile("ldmatrix.sync.aligned.m8n8.x4.shared.b16 {%0,%1,%2,%3},[%4];"
        :"=r"(r[0]),"=r"(r[1]),"=r"(r[2]),"=r"(r[3]):"r"(a));
}
__device__ __forceinline__ void ldsm4t(u32* r, u32 a){
    asm volatile("ldmatrix.sync.aligned.m8n8.x4.trans.shared.b16 {%0,%1,%2,%3},[%4];"
        :"=r"(r[0]),"=r"(r[1]),"=r"(r[2]),"=r"(r[3]):"r"(a));
}
__device__ __forceinline__ void mma_f16(float* c, const u32* a, const u32* b){
    asm volatile("mma.sync.aligned.m16n8k16.row.col.f32.f16.f16.f32 "
        "{%0,%1,%2,%3},{%4,%5,%6,%7},{%8,%9},{%0,%1,%2,%3};"
        :"+f"(c[0]),"+f"(c[1]),"+f"(c[2]),"+f"(c[3])
        :"r"(a[0]),"r"(a[1]),"r"(a[2]),"r"(a[3]),"r"(b[0]),"r"(b[1]));
}
__device__ __forceinline__ void st_pair(__half* H, __half* L, size_t off, float v0, float v1){
    __half h0=__float2half_rn(v0), h1=__float2half_rn(v1);
    __half2 hh; hh.x=h0; hh.y=h1;
    __half2 ll;
    ll.x=__float2half_rn(v0-__half2float(h0));
    ll.y=__float2half_rn(v1-__half2float(h1));
    *(__half2*)(H+off)=hh; *(__half2*)(L+off)=ll;
}

// ---------------- converts ----------------
__global__ void conv_pair(const float* __restrict__ in, __half* __restrict__ hi,
                          __half* __restrict__ lo, int n){
    int i = blockIdx.x*256 + threadIdx.x;
    if (i < n){
        float v = in[i];
        __half h = __float2half_rn(v);
        hi[i]=h; lo[i]=__float2half_rn(v-__half2float(h));
    }
}
__global__ void conv_hi(const float* __restrict__ in, __half* __restrict__ hi, int n){
    int i = blockIdx.x*256 + threadIdx.x;
    if (i < n) hi[i]=__float2half_rn(in[i]);
}
__global__ void conv_gen_k(const float* __restrict__ gen){
    int idx = blockIdx.x*256 + threadIdx.x;
    int j = idx & (GP-1);
    int r = idx >> 11;
    float v = (j < GW) ? gen[(size_t)r*GW + j] : 0.f;
    g_gh[idx]=__float2half_rn(v);
}

// ---------------------------------------------------------------------------
// NT GEMM (projections): C[8192,1024] = A @ B^T. Block 256x128, 8 warps,
// warp tile 64x64, fp16 2-term (A hi/lo), BK=16 double-buffered.
// emit: 0 = fp32 to Cf, 1 = pair to Chg/Clg, 2 = hi-only to Chg.
// Dynamic smem 61440B: A hi [2][256][24], A lo [2][256][24], B [2][128][24].
// ---------------------------------------------------------------------------
#define NT2_SMEM 61440

__global__ __launch_bounds__(256) void mma_nt2(
    const __half* __restrict__ Ahg, const __half* __restrict__ Alg,
    const __half* __restrict__ Bhg,
    float* __restrict__ Cf, __half* __restrict__ Chg, __half* __restrict__ Clg,
    int emit)
{
    extern __shared__ __align__(16) char dsm[];
    __half* sAh = (__half*)dsm;                   // [2][256][24]
    __half* sAl = (__half*)(dsm + 24576);
    __half* sB  = (__half*)(dsm + 49152);         // [2][128][24]
    const int tid=threadIdx.x, lane=tid&31, wid=tid>>5;
    const int wm=wid>>1, wn=wid&1;
    const int m0=blockIdx.y*256, n0=blockIdx.x*128;

    // loaders: A rows lr and lr+128 (2 uint4 each for hi/lo); B row lr (1 uint4)
    const int lr=tid>>1, lc8=(tid&1)*8;
    const __half* Ah0=Ahg+(size_t)(m0+lr)*DD+lc8;
    const __half* Ah1=Ahg+(size_t)(m0+lr+128)*DD+lc8;
    const __half* Al0=Alg+(size_t)(m0+lr)*DD+lc8;
    const __half* Al1=Alg+(size_t)(m0+lr+128)*DD+lc8;
    const __half* Bp =Bhg+(size_t)(n0+lr)*DD+lc8;

    float acc[4][8][4];
#pragma unroll
    for(int i=0;i<4;i++)
#pragma unroll
    for(int j=0;j<8;j++)
#pragma unroll
    for(int k2=0;k2<4;k2++) acc[i][j][k2]=0.f;

    uint4 ph0=*(const uint4*)Ah0, ph1=*(const uint4*)Ah1;
    uint4 pl0=*(const uint4*)Al0, pl1=*(const uint4*)Al1;
    uint4 pb =*(const uint4*)Bp;
    *(uint4*)&sAh[lr*24+lc8]        = ph0;
    *(uint4*)&sAh[(lr+128)*24+lc8]  = ph1;
    *(uint4*)&sAl[lr*24+lc8]        = pl0;
    *(uint4*)&sAl[(lr+128)*24+lc8]  = pl1;
    *(uint4*)&sB [lr*24+lc8]        = pb;
    __syncthreads();

    const int nst = DD/16;   // 64
    int buf = 0;
    const int g=lane>>3;
    const int arow=((g&1)<<3)+(lane&7), acol=(g>>1)<<3;
    const int brow=((g>>1)<<3)+(lane&7), bcol=(g&1)<<3;
    const int aoff = 256*24, boff = 128*24;      // per-buffer half offsets

    for(int it=0; it<nst; it++){
        if(it+1<nst){
            const int kb=(it+1)*16;
            ph0=*(const uint4*)(Ah0+kb); ph1=*(const uint4*)(Ah1+kb);
            pl0=*(const uint4*)(Al0+kb); pl1=*(const uint4*)(Al1+kb);
            pb =*(const uint4*)(Bp +kb);
        }
        u32 afh[4][4], afl[4][4];
#pragma unroll
        for(int mt=0;mt<4;mt++){
            ldsm4(afh[mt], smaddr(&sAh[buf*aoff+(wm*64+mt*16+arow)*24+acol]));
            ldsm4(afl[mt], smaddr(&sAl[buf*aoff+(wm*64+mt*16+arow)*24+acol]));
        }
        u32 bfh[4][4];
#pragma unroll
        for(int np=0;np<4;np++)
            ldsm4(bfh[np], smaddr(&sB[buf*boff+(wn*64+np*16+brow)*24+bcol]));
#pragma unroll
        for(int mt=0;mt<4;mt++)
#pragma unroll
        for(int np=0;np<4;np++)
#pragma unroll
        for(int hf=0;hf<2;hf++){
            int nt=np*2+hf;
            mma_f16(acc[mt][nt], afh[mt], &bfh[np][hf*2]);
            mma_f16(acc[mt][nt], afl[mt], &bfh[np][hf*2]);
        }
        if(it+1<nst){
            buf^=1;
            *(uint4*)&sAh[buf*aoff+lr*24+lc8]       = ph0;
            *(uint4*)&sAh[buf*aoff+(lr+128)*24+lc8] = ph1;
            *(uint4*)&sAl[buf*aoff+lr*24+lc8]       = pl0;
            *(uint4*)&sAl[buf*aoff+(lr+128)*24+lc8] = pl1;
            *(uint4*)&sB [buf*boff+lr*24+lc8]       = pb;
            __syncthreads();
        }
    }
#pragma unroll
    for(int mt=0;mt<4;mt++)
#pragma unroll
    for(int nt=0;nt<8;nt++){
        int r=m0+wm*64+mt*16+(lane>>2);
        int c=n0+wn*64+nt*8+((lane&3)<<1);
        float* a4=acc[mt][nt];
        if(emit==1){
            st_pair(Chg,Clg,(size_t)r*DD+c,a4[0],a4[1]);
            st_pair(Chg,Clg,(size_t)(r+8)*DD+c,a4[2],a4[3]);
        } else if(emit==2){
            __half2 h0; h0.x=__float2half_rn(a4[0]); h0.y=__float2half_rn(a4[1]);
            __half2 h1; h1.x=__float2half_rn(a4[2]); h1.y=__float2half_rn(a4[3]);
            *(__half2*)(Chg+(size_t)r*DD+c)=h0;
            *(__half2*)(Chg+(size_t)(r+8)*DD+c)=h1;
        } else {
            *(float2*)(Cf+(size_t)r*DD+c)=make_float2(a4[0],a4[1]);
            *(float2*)(Cf+(size_t)(r+8)*DD+c)=make_float2(a4[2],a4[3]);
        }
    }
}

// ---------------------------------------------------------------------------
// Score GEMM (mma.sync fp16x2): wfull[bh,l,j] = sum_k q[b,l,h*DH+k]*gen[h,k,j]
// Band restriction: tile used iff 769 <= l0+j0 <= 2046.
// ---------------------------------------------------------------------------
__global__ __launch_bounds__(256) void mma_score(){
    const int l0=blockIdx.y*128, j0=blockIdx.x*128;
    if (l0 + j0 < 769 || l0 + j0 > 2046) return;
    __shared__ __align__(16) __half Ah[2][128][24], Al[2][128][24];
    __shared__ __align__(16) __half Bh[2][16][136];
    const int tid=threadIdx.x, lane=tid&31, wid=tid>>5, wm=wid>>1, wn=wid&1;
    const int bh=blockIdx.z, b=bh>>2, h=bh&3;
    const int lr=tid>>1, lc=(tid&1)<<3;
    const __half* Ahp=g_qh+(size_t)(b*LL+l0+lr)*DD+h*DH+lc;
    const __half* Alp=g_ql+(size_t)(b*LL+l0+lr)*DD+h*DH+lc;
    const int vbr=tid>>4, vbc=(tid&15)<<3;
    const __half* Bhp=g_gh+(size_t)(h*DH+vbr)*GP+j0+vbc;
    float acc[2][8][4];
#pragma unroll
    for(int i=0;i<2;i++)
#pragma unroll
    for(int j=0;j<8;j++)
#pragma unroll
    for(int k2=0;k2<4;k2++) acc[i][j][k2]=0.f;

    uint4 pah=*(const uint4*)Ahp, pal=*(const uint4*)Alp, pbh=*(const uint4*)Bhp;
    *(uint4*)&Ah[0][lr][lc]=pah; *(uint4*)&Al[0][lr][lc]=pal;
    *(uint4*)&Bh[0][vbr][vbc]=pbh;
    __syncthreads();

    const int nst=DH>>4;
    int buf=0;
    const int g=lane>>3;
    const int arow=((g&1)<<3)+(lane&7), acol=(g>>1)<<3;
    const int tbrow=((g&1)<<3)+(lane&7), tbcoff=(g>>1)<<3;
    for(int it=0;it<nst;it++){
        if(it+1<nst){
            pah=*(const uint4*)(Ahp+(it+1)*16); pal=*(const uint4*)(Alp+(it+1)*16);
            pbh=*(const uint4*)(Bhp+(size_t)(it+1)*16*GP);
        }
        u32 afh[2][4], afl[2][4];
#pragma unroll
        for(int mt=0;mt<2;mt++){
            ldsm4(afh[mt], smaddr(&Ah[buf][wm*32+mt*16+arow][acol]));
            ldsm4(afl[mt], smaddr(&Al[buf][wm*32+mt*16+arow][acol]));
        }
        u32 bfh[4][4];
#pragma unroll
        for(int np=0;np<4;np++)
            ldsm4t(bfh[np], smaddr(&Bh[buf][tbrow][wn*64+np*16+tbcoff]));
#pragma unroll
        for(int mt=0;mt<2;mt++)
#pragma unroll
        for(int np=0;np<4;np++)
#pragma unroll
        for(int hf=0;hf<2;hf++){
            int nt=np*2+hf;
            mma_f16(acc[mt][nt], afh[mt], &bfh[np][hf*2]);
            mma_f16(acc[mt][nt], afl[mt], &bfh[np][hf*2]);
        }
        if(it+1<nst){
            buf^=1;
            *(uint4*)&Ah[buf][lr][lc]=pah; *(uint4*)&Al[buf][lr][lc]=pal;
            *(uint4*)&Bh[buf][vbr][vbc]=pbh;
            __syncthreads();
        }
    }
    float* dst=g_wfull+(size_t)bh*LL*GP;
#pragma unroll
    for(int mt=0;mt<2;mt++)
#pragma unroll
    for(int nt=0;nt<8;nt++){
        int r=l0+wm*32+mt*16+(lane>>2);
        int c=j0+wn*64+nt*8+((lane&3)<<1);
        float* a4=acc[mt][nt];
        *(float2*)(dst+(size_t)r*GP+c)=make_float2(a4[0],a4[1]);
        *(float2*)(dst+(size_t)(r+8)*GP+c)=make_float2(a4[2],a4[3]);
    }
}

// ---------------------------------------------------------------------------
// Fused Toeplitz gather + cumsum + relu + mask; W emitted as fp16 pair.
// ---------------------------------------------------------------------------
__global__ __launch_bounds__(256) void cumsum_fuse(){
    const int bh=blockIdx.y;
    const int i=blockIdx.x*256+threadIdx.x;
    const float* src=g_wfull+(size_t)bh*LL*GP+1023+i;
    __half* wh=g_Wh+(size_t)bh*LL*LL+i;
    __half* wl=g_Wl+(size_t)bh*LL*LL+i;
    float acc=0.f;
    for(int l=0;l<LL;l+=8){
        float vb[8];
#pragma unroll
        for(int u=0;u<8;u++) vb[u]=src[(size_t)(l+u)*2047];
#pragma unroll
        for(int u=0;u<8;u++){
            acc+=vb[u];
            float m=(i<=l+u)?fmaxf(acc,0.f):0.f;
            __half hh=__float2half_rn(m);
            wh[(size_t)(l+u)*LL]=hh;
            wl[(size_t)(l+u)*LL]=__float2half_rn(m-__half2float(hh));
        }
    }
}

// ---------------------------------------------------------------------------
__global__ __launch_bounds__(256) void rowsum_k(){
    const int bh=blockIdx.y, l=blockIdx.x;
    const __half* wh=g_Wh+(size_t)(bh*LL+l)*LL;
    const __half* wl=g_Wl+(size_t)(bh*LL+l)*LL;
    float s=0.f;
    for(int i=threadIdx.x;i<=l;i+=256)
        s+=__half2float(wh[i])+__half2float(wl[i]);
#pragma unroll
    for(int o=16;o>0;o>>=1) s+=__shfl_xor_sync(0xffffffffu,s,o);
    __shared__ float red[8];
    if((threadIdx.x&31)==0) red[threadIdx.x>>5]=s;
    __syncthreads();
    if(threadIdx.x<8){
        s=red[threadIdx.x];
#pragma unroll
        for(int o=4;o>0;o>>=1) s+=__shfl_xor_sync(0xffu,s,o);
        if(threadIdx.x==0) g_rs[bh*LL+l]=s;
    }
}

// ---------------------------------------------------------------------------
// AV GEMM (mma.sync fp16x2): attn = normalize(W) @ v (causal).
// ---------------------------------------------------------------------------
__global__ __launch_bounds__(256) void mma_av(){
    __shared__ __align__(16) __half Ah[2][128][24], Al[2][128][24];
    __shared__ __align__(16) __half Bh[2][16][136];
    const int tid=threadIdx.x, lane=tid&31, wid=tid>>5, wm=wid>>1, wn=wid&1;
    const int bh=blockIdx.z, b=bh>>2, h=bh&3;
    const int l0=blockIdx.y*128, n0=blockIdx.x*128;
    const int lr=tid>>1, lc=(tid&1)<<3;
    const __half* Ahp=g_Wh+(size_t)(bh*LL+l0+lr)*LL+lc;
    const __half* Alp=g_Wl+(size_t)(bh*LL+l0+lr)*LL+lc;
    const int vbr=tid>>4, vbc=(tid&15)<<3;
    const __half* Bhp=g_vh+(size_t)(b*LL+vbr)*DD+h*DH+n0+vbc;
    float acc[2][8][4];
#pragma unroll
    for(int i=0;i<2;i++)
#pragma unroll
    for(int j=0;j<8;j++)
#pragma unroll
    for(int k2=0;k2<4;k2++) acc[i][j][k2]=0.f;

    uint4 pah=*(const uint4*)Ahp, pal=*(const uint4*)Alp, pbh=*(const uint4*)Bhp;
    *(uint4*)&Ah[0][lr][lc]=pah; *(uint4*)&Al[0][lr][lc]=pal;
    *(uint4*)&Bh[0][vbr][vbc]=pbh;
    __syncthreads();

    const int nst=(l0+128)>>4;
    int buf=0;
    const int g=lane>>3;
    const int arow=((g&1)<<3)+(lane&7), acol=(g>>1)<<3;
    const int tbrow=((g&1)<<3)+(lane&7), tbcoff=(g>>1)<<3;
    for(int it=0;it<nst;it++){
        if(it+1<nst){
            pah=*(const uint4*)(Ahp+(it+1)*16); pal=*(const uint4*)(Alp+(it+1)*16);
            pbh=*(const uint4*)(Bhp+(size_t)(it+1)*16*DD);
        }
        u32 afh[2][4], afl[2][4];
#pragma unroll
        for(int mt=0;mt<2;mt++){
            ldsm4(afh[mt], smaddr(&Ah[buf][wm*32+mt*16+arow][acol]));
            ldsm4(afl[mt], smaddr(&Al[buf][wm*32+mt*16+arow][acol]));
        }
        u32 bfh[4][4];
#pragma unroll
        for(int np=0;np<4;np++)
            ldsm4t(bfh[np], smaddr(&Bh[buf][tbrow][wn*64+np*16+tbcoff]));
#pragma unroll
        for(int mt=0;mt<2;mt++)
#pragma unroll
        for(int np=0;np<4;np++)
#pragma unroll
        for(int hf=0;hf<2;hf++){
            int nt=np*2+hf;
            mma_f16(acc[mt][nt], afh[mt], &bfh[np][hf*2]);
            mma_f16(acc[mt][nt], afl[mt], &bfh[np][hf*2]);
        }
        if(it+1<nst){
            buf^=1;
            *(uint4*)&Ah[buf][lr][lc]=pah; *(uint4*)&Al[buf][lr][lc]=pal;
            *(uint4*)&Bh[buf][vbr][vbc]=pbh;
            __syncthreads();
        }
    }
#pragma unroll
    for(int mt=0;mt<2;mt++)
#pragma unroll
    for(int nt=0;nt<8;nt++){
        int r=l0+wm*32+mt*16+(lane>>2);
        int cD=h*DH+n0+wn*64+nt*8+((lane&3)<<1);
        float s0=1.f/(g_rs[bh*LL+r]+1e-8f);
        float s1=1.f/(g_rs[bh*LL+r+8]+1e-8f);
        float* a4=acc[mt][nt];
        st_pair(g_ath,g_atl,(size_t)(b*LL+r)*DD+cD,a4[0]*s0,a4[1]*s0);
        st_pair(g_ath,g_atl,(size_t)(b*LL+r+8)*DD+cD,a4[2]*s1,a4[3]*s1);
    }
}

// ---------------------------------------------------------------------------
extern "C" void kernel_launch(void* const* d_in, const int* in_sizes, int n_in,
                              void* d_out, int out_size) {
    const float* x   = (const float*)d_in[0];
    const float* gen = (const float*)d_in[1];
    const float* Wq  = (const float*)d_in[2];
    const float* Wv  = (const float*)d_in[3];
    const float* Wp  = (const float*)d_in[4];
    float* out = (float*)d_out;

    __half *xh,*xl,*wqh,*wvh,*wph,*qh,*ql,*vh,*ath,*atl;
    cudaGetSymbolAddress((void**)&xh,  g_xh);  cudaGetSymbolAddress((void**)&xl,  g_xl);
    cudaGetSymbolAddress((void**)&wqh, g_wqh);
    cudaGetSymbolAddress((void**)&wvh, g_wvh);
    cudaGetSymbolAddress((void**)&wph, g_wph);
    cudaGetSymbolAddress((void**)&qh,  g_qh);  cudaGetSymbolAddress((void**)&ql,  g_ql);
    cudaGetSymbolAddress((void**)&vh,  g_vh);
    cudaGetSymbolAddress((void**)&ath, g_ath); cudaGetSymbolAddress((void**)&atl, g_atl);

    cudaFuncSetAttribute(mma_nt2, cudaFuncAttributeMaxDynamicSharedMemorySize, NT2_SMEM);

    conv_pair<<<(BB*LL*DD)/256,256>>>(x, xh, xl, BB*LL*DD);
    conv_hi<<<(DD*DD)/256,256>>>(Wq, wqh, DD*DD);
    conv_hi<<<(DD*DD)/256,256>>>(Wv, wvh, DD*DD);
    conv_hi<<<(DD*DD)/256,256>>>(Wp, wph, DD*DD);
    conv_gen_k<<<(HH*DH*GP)/256,256>>>(gen);

    dim3 gproj(DD/128, BB*LL/256);   // (8, 32)
    mma_nt2<<<gproj, 256, NT2_SMEM>>>(xh, xl, wqh, nullptr, qh, ql, 1);
    mma_nt2<<<gproj, 256, NT2_SMEM>>>(xh, xl, wvh, nullptr, vh, nullptr, 2);

    mma_score<<<dim3(GP/128, LL/128, BB*HH),256>>>();
    cumsum_fuse<<<dim3(LL/256, BB*HH),256>>>();
    rowsum_k<<<dim3(LL, BB*HH),256>>>();
    mma_av<<<dim3(DH/128, LL/128, BB*HH),256>>>();

    mma_nt2<<<gproj, 256, NT2_SMEM>>>(ath, atl, wph, out, nullptr, nullptr, 0);
}